// round 6
// baseline (speedup 1.0000x reference)
#include <cuda_runtime.h>
#include <cuda_bf16.h>
#include <cstdint>

// Problem constants
#define BATCH   2
#define S_LEN   2048
#define D_MODEL 1024
#define NH      16
#define HD      64
#define WINDOW  256
#define TOKENS  (BATCH * S_LEN)               // 4096
#define OUT_ELEMS ((size_t)TOKENS * D_MODEL)  // 4194304
#define KEFF    3072                          // 3 * 1024 (hi/hi/lo split along K)
#define NCHUNK  48                            // KEFF / 64

// ---------------- device scratch (allocation-free rule) ----------------
__device__ __align__(128) float g_q [BATCH * NH * S_LEN * HD];
__device__ __align__(128) __nv_bfloat16 g_xhat[(size_t)TOKENS * KEFF];      // [A_hi|A_hi|A_lo]
__device__ __align__(128) __nv_bfloat16 g_ahat[(size_t)TOKENS * KEFF];
__device__ __align__(128) __nv_bfloat16 g_wat [(size_t)3 * D_MODEL * KEFF]; // W^T split [B_hi|B_lo|B_hi]
__device__ __align__(128) __nv_bfloat16 g_wpt [(size_t)D_MODEL * KEFF];

// ---------------- helpers ----------------
__device__ __forceinline__ uint32_t smem_u32(const void* p) {
    uint32_t a;
    asm("{ .reg .u64 t; cvta.to.shared.u64 t, %1; cvt.u32.u64 %0, t; }" : "=r"(a) : "l"(p));
    return a;
}
__device__ __forceinline__ void cp16(uint32_t saddr, const void* g) {
    asm volatile("cp.async.cg.shared.global [%0], [%1], 16;" :: "r"(saddr), "l"(g));
}
#define CP_COMMIT() asm volatile("cp.async.commit_group;" ::: "memory")
#define CP_WAIT1()  asm volatile("cp.async.wait_group 1;" ::: "memory")
#define CP_WAIT0()  asm volatile("cp.async.wait_group 0;" ::: "memory")

__device__ __forceinline__ void ldmx4(uint32_t* r, uint32_t addr) {
    asm volatile("ldmatrix.sync.aligned.m8n8.x4.shared.b16 {%0,%1,%2,%3}, [%4];"
                 : "=r"(r[0]), "=r"(r[1]), "=r"(r[2]), "=r"(r[3]) : "r"(addr));
}
__device__ __forceinline__ void mma16816(float* c, const uint32_t* a, const uint32_t* b) {
    asm volatile(
        "mma.sync.aligned.m16n8k16.row.col.f32.bf16.bf16.f32 "
        "{%0,%1,%2,%3}, {%4,%5,%6,%7}, {%8,%9}, {%0,%1,%2,%3};"
        : "+f"(c[0]), "+f"(c[1]), "+f"(c[2]), "+f"(c[3])
        : "r"(a[0]), "r"(a[1]), "r"(a[2]), "r"(a[3]), "r"(b[0]), "r"(b[1]));
}

// ---------------- split conversion kernels ----------------
// fp32 [M,1024] -> bf16 [M,3072] segments [hi | hi | lo]
__global__ void convA_k(const float* __restrict__ A, __nv_bfloat16* __restrict__ O, int total)
{
    int idx = blockIdx.x * blockDim.x + threadIdx.x;
    if (idx >= total) return;
    int m = idx >> 10, k = idx & 1023;
    float v = A[idx];
    __nv_bfloat16 hi = __float2bfloat16(v);
    __nv_bfloat16 lo = __float2bfloat16(v - __bfloat162float(hi));
    __nv_bfloat16* row = O + (size_t)m * KEFF;
    row[k] = hi; row[1024 + k] = hi; row[2048 + k] = lo;
}
// W fp32 [1024, N] row-major -> Bt bf16 [N, 3072] segments [hi | lo | hi] (transpose)
__global__ void convBt_k(const float* __restrict__ W, __nv_bfloat16* __restrict__ O, int N)
{
    __shared__ float tile[32][33];
    int k0 = blockIdx.y * 32, n0 = blockIdx.x * 32;
    int tx = threadIdx.x, ty = threadIdx.y;
    tile[ty][tx] = W[(size_t)(k0 + ty) * N + n0 + tx];
    __syncthreads();
    float v = tile[tx][ty];
    __nv_bfloat16 hi = __float2bfloat16(v);
    __nv_bfloat16 lo = __float2bfloat16(v - __bfloat162float(hi));
    __nv_bfloat16* row = O + (size_t)(n0 + ty) * KEFF;
    int k = k0 + tx;
    row[k] = hi; row[1024 + k] = lo; row[2048 + k] = hi;
}

// ---------------- mma.sync GEMM: C(4096, N) = Ahat(M,3072) . Bt(N,3072)^T ----------------
// Block 128x128, K-chunk 64, 8 warps (2Mx4N), warp tile 64x32.
// 3-stage cp.async smem pipeline + register-level fragment double-buffering:
// ldmatrix for k-step ks+1 issues before the MMAs of ks, hiding LDSM latency.
#define TILE_BYTES  18432         // 128 rows * 144B
#define BUF_BYTES   36864         // A + B
#define GEMM_SMEM   110592        // 3 buffers

template<int MODE>
__global__ __launch_bounds__(256, 1) void gemm_mma(const __nv_bfloat16* __restrict__ A,
                                                   const __nv_bfloat16* __restrict__ Bt,
                                                   const float* __restrict__ bias,
                                                   float* __restrict__ C,
                                                   float* __restrict__ KV)
{
    extern __shared__ char smem[];
    const uint32_t sb = smem_u32(smem);
    const int tid = threadIdx.x;
    const int wid = tid >> 5, lid = tid & 31;
    const int m0 = blockIdx.y * 128, n0 = blockIdx.x * 128;
    const int mbase = (wid & 1) * 64;     // warp M offset
    const int nbase = (wid >> 1) * 32;    // warp N offset

    const char* Abase = (const char*)(A  + (size_t)m0 * KEFF);
    const char* Bbase = (const char*)(Bt + (size_t)n0 * KEFF);

    // per-warp invariant parts of the ldmatrix addresses
    const uint32_t a_row_off = (uint32_t)((mbase + ((lid >> 3) & 1) * 8 + (lid & 7)) * 144
                                          + ((lid >> 4) * 8) * 2);
    const uint32_t b_row_off = (uint32_t)((nbase + ((lid >> 4) & 1) * 8 + (lid & 7)) * 144
                                          + (((lid >> 3) & 1) * 8) * 2);

    float acc[4][4][4];
#pragma unroll
    for (int mt = 0; mt < 4; mt++)
#pragma unroll
        for (int nt = 0; nt < 4; nt++)
#pragma unroll
            for (int i = 0; i < 4; i++) acc[mt][nt][i] = 0.f;

#define PREFETCH(c, buf)                                                          \
    {                                                                             \
        const size_t kbyte = (size_t)(c) * 128;                                   \
        const uint32_t abuf = sb + (buf) * BUF_BYTES;                             \
        const uint32_t bbuf = abuf + TILE_BYTES;                                  \
        _Pragma("unroll")                                                         \
        for (int i = 0; i < 4; i++) {                                             \
            int idx = tid + i * 256;                                              \
            int row = idx >> 3, seg = idx & 7;                                    \
            uint32_t so = row * 144 + seg * 16;                                   \
            cp16(abuf + so, Abase + (size_t)row * (KEFF * 2) + kbyte + seg * 16); \
            cp16(bbuf + so, Bbase + (size_t)row * (KEFF * 2) + kbyte + seg * 16); \
        }                                                                         \
    }

    // load A/B fragments for k-step `ks` of the tile at (abuf,bbuf) into slot s
#define LOAD_FRAGS(s, abuf, bbuf, ks)                                             \
    {                                                                             \
        const uint32_t kb = (uint32_t)(ks) * 32;  /* 16 bf16 = 32B */             \
        _Pragma("unroll")                                                         \
        for (int mt = 0; mt < 4; mt++)                                            \
            ldmx4(ar[s][mt], (abuf) + a_row_off + mt * (16 * 144) + kb);          \
        _Pragma("unroll")                                                         \
        for (int p = 0; p < 2; p++) {                                             \
            uint32_t r[4];                                                        \
            ldmx4(r, (bbuf) + b_row_off + p * (16 * 144) + kb);                   \
            br[s][p * 2][0] = r[0]; br[s][p * 2][1] = r[1];                       \
            br[s][p * 2 + 1][0] = r[2]; br[s][p * 2 + 1][1] = r[3];               \
        }                                                                         \
    }

    PREFETCH(0, 0); CP_COMMIT();
    PREFETCH(1, 1); CP_COMMIT();

    uint32_t ar[2][4][4];
    uint32_t br[2][4][2];

    int buf = 0;
    for (int c = 0; c < NCHUNK; c++) {
        if (c == NCHUNK - 1) { CP_WAIT0(); } else { CP_WAIT1(); }
        __syncthreads();   // chunk c landed; all warps done consuming chunk c-1
        const uint32_t abuf = sb + buf * BUF_BYTES;
        const uint32_t bbuf = abuf + TILE_BYTES;

        // head: fragments for ks=0, then kick off the smem prefetch (its issue
        // cost overlaps the first LDSM latency)
        LOAD_FRAGS(0, abuf, bbuf, 0);
        if (c + 2 < NCHUNK) {
            int nbuf = buf + 2; if (nbuf >= 3) nbuf -= 3;
            PREFETCH(c + 2, nbuf);
            CP_COMMIT();
        }

#pragma unroll
        for (int ks = 0; ks < 4; ks++) {
            const int cur = ks & 1;
            if (ks < 3) LOAD_FRAGS(cur ^ 1, abuf, bbuf, ks + 1);
#pragma unroll
            for (int mt = 0; mt < 4; mt++)
#pragma unroll
                for (int nt = 0; nt < 4; nt++)
                    mma16816(acc[mt][nt], ar[cur][mt], br[cur][nt]);
        }
        if (++buf == 3) buf = 0;
    }
#undef PREFETCH
#undef LOAD_FRAGS

    // ---- epilogue ----
    const int lrow = lid >> 2;           // 0..7
    const int lcol = (lid & 3) * 2;      // 0,2,4,6
#pragma unroll
    for (int mt = 0; mt < 4; mt++) {
        const int gm = m0 + mbase + mt * 16 + lrow;
#pragma unroll
        for (int nt = 0; nt < 4; nt++) {
            const int gn = n0 + nbase + nt * 8 + lcol;
            if (MODE == 0) {
                const float b0 = bias[gn], b1 = bias[gn + 1];
                float2 v0 = {acc[mt][nt][0] + b0, acc[mt][nt][1] + b1};
                float2 v1 = {acc[mt][nt][2] + b0, acc[mt][nt][3] + b1};
                *(float2*)&C[(size_t)gm * D_MODEL + gn] = v0;
                *(float2*)&C[(size_t)(gm + 8) * D_MODEL + gn] = v1;
            } else {
                // QKV scatter: Q -> g_q, K/V -> present tail of d_out (KV)
#pragma unroll
                for (int e = 0; e < 4; e++) {
                    const int row = gm + (e >> 1) * 8;
                    const int f   = gn + (e & 1);
                    const float v = acc[mt][nt][e] + bias[f];
                    const int bb = row >> 11, s = row & 2047;
                    const int sec = f >> 10, fr = f & 1023;
                    const int h = fr >> 6, dd = fr & 63;
                    if (sec == 0)
                        g_q[(((size_t)bb * NH + h) * S_LEN + s) * HD + dd] = v;
                    else
                        KV[((((size_t)bb * 2 + (sec - 1)) * NH + h) * S_LEN + s) * HD + dd] = v;
                }
            }
        }
    }
}

// ---------------- sliding-window attention ----------------
// Reads K/V from the `present` tail of d_out; writes split bf16 directly
// into g_ahat (fused convA).
#define ATTN_SMEM_FLOATS (2 * 64 * 65 + 64 * 321 + 64)
#define ATTN_SMEM_BYTES  (ATTN_SMEM_FLOATS * 4)

__global__ __launch_bounds__(256) void attn_k(const float* __restrict__ KV)
{
    extern __shared__ float sm[];
    float (*Qs)[65]  = (float(*)[65])sm;
    float (*Ks)[65]  = (float(*)[65])(sm + 64 * 65);
    float (*Ss)[321] = (float(*)[321])(sm + 2 * 64 * 65);
    float* rinv      = sm + 2 * 64 * 65 + 64 * 321;

    const int bid = blockIdx.x;
    const int qt = bid & 31;
    const int h  = (bid >> 5) & 15;
    const int b  = bid >> 9;
    const int qs = qt * 64;

    const int tid = threadIdx.x;
    const int tx = tid & 15;
    const int ty = tid >> 4;
    const float scale = 0.125f;

    const float* Qg = g_q + (((size_t)b * NH + h) * S_LEN) * HD;
    const float* Kg = KV + ((((size_t)b * 2 + 0) * NH + h) * S_LEN) * HD;
    const float* Vg = KV + ((((size_t)b * 2 + 1) * NH + h) * S_LEN) * HD;

    for (int idx = tid; idx < 64 * 64; idx += 256) {
        const int i = idx >> 6, d = idx & 63;
        Qs[i][d] = Qg[(size_t)(qs + i) * HD + d] * scale;
    }

    for (int kt = 0; kt < 5; kt++) {
        const int ks = qs - 256 + kt * 64;
        if (ks + 64 <= 0) {
            for (int idx = tid; idx < 64 * 64; idx += 256)
                Ss[idx >> 6][kt * 64 + (idx & 63)] = -1e30f;
            continue;
        }
        __syncthreads();
        for (int idx = tid; idx < 64 * 64; idx += 256) {
            const int j = idx >> 6, d = idx & 63;
            const int gj = ks + j;
            Ks[j][d] = (gj >= 0) ? Kg[(size_t)gj * HD + d] : 0.f;
        }
        __syncthreads();

        float s[4][4];
#pragma unroll
        for (int r = 0; r < 4; r++)
#pragma unroll
            for (int c = 0; c < 4; c++) s[r][c] = 0.f;
        const int i0 = ty * 4, j0 = tx * 4;
#pragma unroll 8
        for (int d = 0; d < 64; d++) {
            float q[4], kk[4];
#pragma unroll
            for (int r = 0; r < 4; r++) q[r] = Qs[i0 + r][d];
#pragma unroll
            for (int c = 0; c < 4; c++) kk[c] = Ks[j0 + c][d];
#pragma unroll
            for (int r = 0; r < 4; r++)
#pragma unroll
                for (int c = 0; c < 4; c++) s[r][c] += q[r] * kk[c];
        }
#pragma unroll
        for (int r = 0; r < 4; r++) {
            const int gi = qs + i0 + r;
#pragma unroll
            for (int c = 0; c < 4; c++) {
                const int gj = ks + j0 + c;
                const bool ok = (gj >= 0) && (gj <= gi) && (gj > gi - WINDOW);
                Ss[i0 + r][kt * 64 + j0 + c] = ok ? s[r][c] : -1e30f;
            }
        }
    }
    __syncthreads();

    if (tid < 64) {
        float mx = -1e30f;
        for (int c = 0; c < 320; c++) mx = fmaxf(mx, Ss[tid][c]);
        float sum = 0.f;
        for (int c = 0; c < 320; c++) {
            const float e = __expf(Ss[tid][c] - mx);
            Ss[tid][c] = e;
            sum += e;
        }
        rinv[tid] = 1.f / sum;
    }

    float o[4][4];
#pragma unroll
    for (int r = 0; r < 4; r++)
#pragma unroll
        for (int c = 0; c < 4; c++) o[r][c] = 0.f;
    const int i0 = ty * 4, d0 = tx * 4;

    for (int kt = 0; kt < 5; kt++) {
        const int ks = qs - 256 + kt * 64;
        if (ks + 64 <= 0) continue;
        __syncthreads();
        for (int idx = tid; idx < 64 * 64; idx += 256) {
            const int j = idx >> 6, d = idx & 63;
            const int gj = ks + j;
            Ks[j][d] = (gj >= 0) ? Vg[(size_t)gj * HD + d] : 0.f;
        }
        __syncthreads();
#pragma unroll 8
        for (int j = 0; j < 64; j++) {
            float p[4], v[4];
#pragma unroll
            for (int r = 0; r < 4; r++) p[r] = Ss[i0 + r][kt * 64 + j];
#pragma unroll
            for (int c = 0; c < 4; c++) v[c] = Ks[j][d0 + c];
#pragma unroll
            for (int r = 0; r < 4; r++)
#pragma unroll
                for (int c = 0; c < 4; c++) o[r][c] += p[r] * v[c];
        }
    }

    // fused epilogue: write hi/hi/lo split bf16 straight into g_ahat
#pragma unroll
    for (int r = 0; r < 4; r++) {
        const float ri = rinv[i0 + r];
        const size_t m = (size_t)b * S_LEN + qs + i0 + r;
        __nv_bfloat16* row = g_ahat + m * KEFF;
        const int k = h * HD + d0;
#pragma unroll
        for (int c = 0; c < 4; c++) {
            const float v = o[r][c] * ri;
            const __nv_bfloat16 hi = __float2bfloat16(v);
            const __nv_bfloat16 lo = __float2bfloat16(v - __bfloat162float(hi));
            row[k + c] = hi;
            row[1024 + k + c] = hi;
            row[2048 + k + c] = lo;
        }
    }
}

// ---------------------------------------------------------------------------
extern "C" void kernel_launch(void* const* d_in, const int* in_sizes, int n_in,
                              void* d_out, int out_size)
{
    const float* x      = (const float*)d_in[0];
    const float* w_attn = (const float*)d_in[1];
    const float* b_attn = (const float*)d_in[2];
    const float* w_proj = (const float*)d_in[3];
    const float* b_proj = (const float*)d_in[4];
    float* out = (float*)d_out;
    float* kv  = out + OUT_ELEMS;   // `present` tail of the flattened output

    cudaFuncSetAttribute(attn_k, cudaFuncAttributeMaxDynamicSharedMemorySize, ATTN_SMEM_BYTES);
    cudaFuncSetAttribute(gemm_mma<0>, cudaFuncAttributeMaxDynamicSharedMemorySize, GEMM_SMEM);
    cudaFuncSetAttribute(gemm_mma<1>, cudaFuncAttributeMaxDynamicSharedMemorySize, GEMM_SMEM);

    __nv_bfloat16 *xhat, *ahat, *wat, *wpt;
    cudaGetSymbolAddress((void**)&xhat, g_xhat);
    cudaGetSymbolAddress((void**)&ahat, g_ahat);
    cudaGetSymbolAddress((void**)&wat,  g_wat);
    cudaGetSymbolAddress((void**)&wpt,  g_wpt);

    // 1) split conversions of inputs
    convA_k<<<(TOKENS * 1024 + 255) / 256, 256>>>(x, xhat, TOKENS * 1024);
    {
        dim3 blk(32, 32);
        convBt_k<<<dim3(3 * D_MODEL / 32, D_MODEL / 32), blk>>>(w_attn, wat, 3 * D_MODEL);
        convBt_k<<<dim3(D_MODEL / 32, D_MODEL / 32),     blk>>>(w_proj, wpt, D_MODEL);
    }

    // 2) QKV projection: Q -> g_q, K/V -> present tail of d_out
    gemm_mma<1><<<dim3(3 * D_MODEL / 128, TOKENS / 128), 256, GEMM_SMEM>>>(
        xhat, wat, b_attn, nullptr, kv);

    // 3) sliding-window attention (reads KV from out tail) -> g_ahat (split bf16)
    attn_k<<<BATCH * NH * (S_LEN / 64), 256, ATTN_SMEM_BYTES>>>(kv);

    // 4) output projection -> d_out head
    gemm_mma<0><<<dim3(D_MODEL / 128, TOKENS / 128), 256, GEMM_SMEM>>>(
        ahat, wpt, b_proj, out, nullptr);
}

// round 7
// speedup vs baseline: 1.1279x; 1.1279x over previous
#include <cuda_runtime.h>
#include <cuda_bf16.h>
#include <cstdint>

// Problem constants
#define BATCH   2
#define S_LEN   2048
#define D_MODEL 1024
#define NH      16
#define HD      64
#define WINDOW  256
#define TOKENS  (BATCH * S_LEN)               // 4096
#define OUT_ELEMS ((size_t)TOKENS * D_MODEL)  // 4194304
#define KEFF    3072                          // 3 * 1024 (hi/hi/lo split along K)
#define NCHUNK  48                            // KEFF / 64

// ---------------- device scratch (allocation-free rule) ----------------
__device__ __align__(128) float g_q [BATCH * NH * S_LEN * HD];
__device__ __align__(128) __nv_bfloat16 g_xhat[(size_t)TOKENS * KEFF];      // [A_hi|A_hi|A_lo]
__device__ __align__(128) __nv_bfloat16 g_ahat[(size_t)TOKENS * KEFF];
__device__ __align__(128) __nv_bfloat16 g_wat [(size_t)3 * D_MODEL * KEFF]; // W^T split [B_hi|B_lo|B_hi]
__device__ __align__(128) __nv_bfloat16 g_wpt [(size_t)D_MODEL * KEFF];

// ---------------- helpers ----------------
__device__ __forceinline__ uint32_t smem_u32(const void* p) {
    uint32_t a;
    asm("{ .reg .u64 t; cvta.to.shared.u64 t, %1; cvt.u32.u64 %0, t; }" : "=r"(a) : "l"(p));
    return a;
}
__device__ __forceinline__ void cp16(uint32_t saddr, const void* g) {
    asm volatile("cp.async.cg.shared.global [%0], [%1], 16;" :: "r"(saddr), "l"(g));
}
#define CP_COMMIT() asm volatile("cp.async.commit_group;" ::: "memory")
#define CP_WAIT1()  asm volatile("cp.async.wait_group 1;" ::: "memory")
#define CP_WAIT0()  asm volatile("cp.async.wait_group 0;" ::: "memory")

__device__ __forceinline__ void ldmx4(uint32_t* r, uint32_t addr) {
    asm volatile("ldmatrix.sync.aligned.m8n8.x4.shared.b16 {%0,%1,%2,%3}, [%4];"
                 : "=r"(r[0]), "=r"(r[1]), "=r"(r[2]), "=r"(r[3]) : "r"(addr));
}
__device__ __forceinline__ void mma16816(float* c, const uint32_t* a, const uint32_t* b) {
    asm volatile(
        "mma.sync.aligned.m16n8k16.row.col.f32.bf16.bf16.f32 "
        "{%0,%1,%2,%3}, {%4,%5,%6,%7}, {%8,%9}, {%0,%1,%2,%3};"
        : "+f"(c[0]), "+f"(c[1]), "+f"(c[2]), "+f"(c[3])
        : "r"(a[0]), "r"(a[1]), "r"(a[2]), "r"(a[3]), "r"(b[0]), "r"(b[1]));
}

// ---------------- split conversion kernels ----------------
// fp32 [M,1024] -> bf16 [M,3072] segments [hi | hi | lo]
__global__ void convA_k(const float* __restrict__ A, __nv_bfloat16* __restrict__ O, int total)
{
    int idx = blockIdx.x * blockDim.x + threadIdx.x;
    if (idx >= total) return;
    int m = idx >> 10, k = idx & 1023;
    float v = A[idx];
    __nv_bfloat16 hi = __float2bfloat16(v);
    __nv_bfloat16 lo = __float2bfloat16(v - __bfloat162float(hi));
    __nv_bfloat16* row = O + (size_t)m * KEFF;
    row[k] = hi; row[1024 + k] = hi; row[2048 + k] = lo;
}
// W fp32 [1024, N] row-major -> Bt bf16 [N, 3072] segments [hi | lo | hi] (transpose)
__global__ void convBt_k(const float* __restrict__ W, __nv_bfloat16* __restrict__ O, int N)
{
    __shared__ float tile[32][33];
    int k0 = blockIdx.y * 32, n0 = blockIdx.x * 32;
    int tx = threadIdx.x, ty = threadIdx.y;
    tile[ty][tx] = W[(size_t)(k0 + ty) * N + n0 + tx];
    __syncthreads();
    float v = tile[tx][ty];
    __nv_bfloat16 hi = __float2bfloat16(v);
    __nv_bfloat16 lo = __float2bfloat16(v - __bfloat162float(hi));
    __nv_bfloat16* row = O + (size_t)(n0 + ty) * KEFF;
    int k = k0 + tx;
    row[k] = hi; row[1024 + k] = lo; row[2048 + k] = hi;
}

// ---------------- mma.sync GEMM: C(4096, N) = Ahat(M,3072) . Bt(N,3072)^T ----------------
// Block 128x128, K-chunk 64, 8 warps (2Mx4N), warp tile 64x32.
// 3-stage cp.async pipeline, ONE __syncthreads per chunk, 2 CTAs/SM
// (launch_bounds caps regs at 128 -> single-buffered fragments).
#define TILE_BYTES  18432         // 128 rows * 144B
#define BUF_BYTES   36864         // A + B
#define GEMM_SMEM   110592        // 3 buffers (2 CTAs/SM: 221 KB of 228 KB)

template<int MODE>
__global__ __launch_bounds__(256, 2) void gemm_mma(const __nv_bfloat16* __restrict__ A,
                                                   const __nv_bfloat16* __restrict__ Bt,
                                                   const float* __restrict__ bias,
                                                   float* __restrict__ C,
                                                   float* __restrict__ KV)
{
    extern __shared__ char smem[];
    const uint32_t sb = smem_u32(smem);
    const int tid = threadIdx.x;
    const int wid = tid >> 5, lid = tid & 31;
    const int m0 = blockIdx.y * 128, n0 = blockIdx.x * 128;
    const int mbase = (wid & 1) * 64;     // warp M offset
    const int nbase = (wid >> 1) * 32;    // warp N offset

    const char* Abase = (const char*)(A  + (size_t)m0 * KEFF);
    const char* Bbase = (const char*)(Bt + (size_t)n0 * KEFF);

    // per-warp invariant parts of the ldmatrix addresses
    const uint32_t a_row_off = (uint32_t)((mbase + ((lid >> 3) & 1) * 8 + (lid & 7)) * 144
                                          + ((lid >> 4) * 8) * 2);
    const uint32_t b_row_off = (uint32_t)((nbase + ((lid >> 4) & 1) * 8 + (lid & 7)) * 144
                                          + (((lid >> 3) & 1) * 8) * 2);

    float acc[4][4][4];
#pragma unroll
    for (int mt = 0; mt < 4; mt++)
#pragma unroll
        for (int nt = 0; nt < 4; nt++)
#pragma unroll
            for (int i = 0; i < 4; i++) acc[mt][nt][i] = 0.f;

#define PREFETCH(c, buf)                                                          \
    {                                                                             \
        const size_t kbyte = (size_t)(c) * 128;                                   \
        const uint32_t abuf = sb + (buf) * BUF_BYTES;                             \
        const uint32_t bbuf = abuf + TILE_BYTES;                                  \
        _Pragma("unroll")                                                         \
        for (int i = 0; i < 4; i++) {                                             \
            int idx = tid + i * 256;                                              \
            int row = idx >> 3, seg = idx & 7;                                    \
            uint32_t so = row * 144 + seg * 16;                                   \
            cp16(abuf + so, Abase + (size_t)row * (KEFF * 2) + kbyte + seg * 16); \
            cp16(bbuf + so, Bbase + (size_t)row * (KEFF * 2) + kbyte + seg * 16); \
        }                                                                         \
    }

    PREFETCH(0, 0); CP_COMMIT();
    PREFETCH(1, 1); CP_COMMIT();

    int buf = 0;
    for (int c = 0; c < NCHUNK; c++) {
        if (c == NCHUNK - 1) { CP_WAIT0(); } else { CP_WAIT1(); }
        __syncthreads();   // chunk c landed; all warps done consuming chunk c-1
        if (c + 2 < NCHUNK) {
            int nbuf = buf + 2; if (nbuf >= 3) nbuf -= 3;
            PREFETCH(c + 2, nbuf);
            CP_COMMIT();
        }
        const uint32_t abuf = sb + buf * BUF_BYTES;
        const uint32_t bbuf = abuf + TILE_BYTES;
#pragma unroll
        for (int ks = 0; ks < 4; ks++) {
            const uint32_t kb = (uint32_t)ks * 32;   // 16 bf16 = 32B
            uint32_t ar[4][4];
            uint32_t br[4][2];
#pragma unroll
            for (int mt = 0; mt < 4; mt++)
                ldmx4(ar[mt], abuf + a_row_off + mt * (16 * 144) + kb);
#pragma unroll
            for (int p = 0; p < 2; p++) {
                uint32_t r[4];
                ldmx4(r, bbuf + b_row_off + p * (16 * 144) + kb);
                br[p * 2][0] = r[0]; br[p * 2][1] = r[1];
                br[p * 2 + 1][0] = r[2]; br[p * 2 + 1][1] = r[3];
            }
#pragma unroll
            for (int mt = 0; mt < 4; mt++)
#pragma unroll
                for (int nt = 0; nt < 4; nt++)
                    mma16816(acc[mt][nt], ar[mt], br[nt]);
        }
        if (++buf == 3) buf = 0;
    }
#undef PREFETCH

    // ---- epilogue ----
    const int lrow = lid >> 2;           // 0..7
    const int lcol = (lid & 3) * 2;      // 0,2,4,6
#pragma unroll
    for (int mt = 0; mt < 4; mt++) {
        const int gm = m0 + mbase + mt * 16 + lrow;
#pragma unroll
        for (int nt = 0; nt < 4; nt++) {
            const int gn = n0 + nbase + nt * 8 + lcol;
            if (MODE == 0) {
                const float b0 = bias[gn], b1 = bias[gn + 1];
                float2 v0 = {acc[mt][nt][0] + b0, acc[mt][nt][1] + b1};
                float2 v1 = {acc[mt][nt][2] + b0, acc[mt][nt][3] + b1};
                *(float2*)&C[(size_t)gm * D_MODEL + gn] = v0;
                *(float2*)&C[(size_t)(gm + 8) * D_MODEL + gn] = v1;
            } else {
                // QKV scatter: Q -> g_q, K/V -> present tail of d_out (KV)
#pragma unroll
                for (int e = 0; e < 4; e++) {
                    const int row = gm + (e >> 1) * 8;
                    const int f   = gn + (e & 1);
                    const float v = acc[mt][nt][e] + bias[f];
                    const int bb = row >> 11, s = row & 2047;
                    const int sec = f >> 10, fr = f & 1023;
                    const int h = fr >> 6, dd = fr & 63;
                    if (sec == 0)
                        g_q[(((size_t)bb * NH + h) * S_LEN + s) * HD + dd] = v;
                    else
                        KV[((((size_t)bb * 2 + (sec - 1)) * NH + h) * S_LEN + s) * HD + dd] = v;
                }
            }
        }
    }
}

// ---------------- sliding-window attention ----------------
// Reads K/V from the `present` tail of d_out; writes split bf16 directly
// into g_ahat (fused convA).
#define ATTN_SMEM_FLOATS (2 * 64 * 65 + 64 * 321 + 64)
#define ATTN_SMEM_BYTES  (ATTN_SMEM_FLOATS * 4)

__global__ __launch_bounds__(256) void attn_k(const float* __restrict__ KV)
{
    extern __shared__ float sm[];
    float (*Qs)[65]  = (float(*)[65])sm;
    float (*Ks)[65]  = (float(*)[65])(sm + 64 * 65);
    float (*Ss)[321] = (float(*)[321])(sm + 2 * 64 * 65);
    float* rinv      = sm + 2 * 64 * 65 + 64 * 321;

    const int bid = blockIdx.x;
    const int qt = bid & 31;
    const int h  = (bid >> 5) & 15;
    const int b  = bid >> 9;
    const int qs = qt * 64;

    const int tid = threadIdx.x;
    const int tx = tid & 15;
    const int ty = tid >> 4;
    const float scale = 0.125f;

    const float* Qg = g_q + (((size_t)b * NH + h) * S_LEN) * HD;
    const float* Kg = KV + ((((size_t)b * 2 + 0) * NH + h) * S_LEN) * HD;
    const float* Vg = KV + ((((size_t)b * 2 + 1) * NH + h) * S_LEN) * HD;

    for (int idx = tid; idx < 64 * 64; idx += 256) {
        const int i = idx >> 6, d = idx & 63;
        Qs[i][d] = Qg[(size_t)(qs + i) * HD + d] * scale;
    }

    for (int kt = 0; kt < 5; kt++) {
        const int ks = qs - 256 + kt * 64;
        if (ks + 64 <= 0) {
            for (int idx = tid; idx < 64 * 64; idx += 256)
                Ss[idx >> 6][kt * 64 + (idx & 63)] = -1e30f;
            continue;
        }
        __syncthreads();
        for (int idx = tid; idx < 64 * 64; idx += 256) {
            const int j = idx >> 6, d = idx & 63;
            const int gj = ks + j;
            Ks[j][d] = (gj >= 0) ? Kg[(size_t)gj * HD + d] : 0.f;
        }
        __syncthreads();

        float s[4][4];
#pragma unroll
        for (int r = 0; r < 4; r++)
#pragma unroll
            for (int c = 0; c < 4; c++) s[r][c] = 0.f;
        const int i0 = ty * 4, j0 = tx * 4;
#pragma unroll 8
        for (int d = 0; d < 64; d++) {
            float q[4], kk[4];
#pragma unroll
            for (int r = 0; r < 4; r++) q[r] = Qs[i0 + r][d];
#pragma unroll
            for (int c = 0; c < 4; c++) kk[c] = Ks[j0 + c][d];
#pragma unroll
            for (int r = 0; r < 4; r++)
#pragma unroll
                for (int c = 0; c < 4; c++) s[r][c] += q[r] * kk[c];
        }
#pragma unroll
        for (int r = 0; r < 4; r++) {
            const int gi = qs + i0 + r;
#pragma unroll
            for (int c = 0; c < 4; c++) {
                const int gj = ks + j0 + c;
                const bool ok = (gj >= 0) && (gj <= gi) && (gj > gi - WINDOW);
                Ss[i0 + r][kt * 64 + j0 + c] = ok ? s[r][c] : -1e30f;
            }
        }
    }
    __syncthreads();

    if (tid < 64) {
        float mx = -1e30f;
        for (int c = 0; c < 320; c++) mx = fmaxf(mx, Ss[tid][c]);
        float sum = 0.f;
        for (int c = 0; c < 320; c++) {
            const float e = __expf(Ss[tid][c] - mx);
            Ss[tid][c] = e;
            sum += e;
        }
        rinv[tid] = 1.f / sum;
    }

    float o[4][4];
#pragma unroll
    for (int r = 0; r < 4; r++)
#pragma unroll
        for (int c = 0; c < 4; c++) o[r][c] = 0.f;
    const int i0 = ty * 4, d0 = tx * 4;

    for (int kt = 0; kt < 5; kt++) {
        const int ks = qs - 256 + kt * 64;
        if (ks + 64 <= 0) continue;
        __syncthreads();
        for (int idx = tid; idx < 64 * 64; idx += 256) {
            const int j = idx >> 6, d = idx & 63;
            const int gj = ks + j;
            Ks[j][d] = (gj >= 0) ? Vg[(size_t)gj * HD + d] : 0.f;
        }
        __syncthreads();
#pragma unroll 8
        for (int j = 0; j < 64; j++) {
            float p[4], v[4];
#pragma unroll
            for (int r = 0; r < 4; r++) p[r] = Ss[i0 + r][kt * 64 + j];
#pragma unroll
            for (int c = 0; c < 4; c++) v[c] = Ks[j][d0 + c];
#pragma unroll
            for (int r = 0; r < 4; r++)
#pragma unroll
                for (int c = 0; c < 4; c++) o[r][c] += p[r] * v[c];
        }
    }

    // fused epilogue: write hi/hi/lo split bf16 straight into g_ahat
#pragma unroll
    for (int r = 0; r < 4; r++) {
        const float ri = rinv[i0 + r];
        const size_t m = (size_t)b * S_LEN + qs + i0 + r;
        __nv_bfloat16* row = g_ahat + m * KEFF;
        const int k = h * HD + d0;
#pragma unroll
        for (int c = 0; c < 4; c++) {
            const float v = o[r][c] * ri;
            const __nv_bfloat16 hi = __float2bfloat16(v);
            const __nv_bfloat16 lo = __float2bfloat16(v - __bfloat162float(hi));
            row[k + c] = hi;
            row[1024 + k + c] = hi;
            row[2048 + k + c] = lo;
        }
    }
}

// ---------------------------------------------------------------------------
extern "C" void kernel_launch(void* const* d_in, const int* in_sizes, int n_in,
                              void* d_out, int out_size)
{
    const float* x      = (const float*)d_in[0];
    const float* w_attn = (const float*)d_in[1];
    const float* b_attn = (const float*)d_in[2];
    const float* w_proj = (const float*)d_in[3];
    const float* b_proj = (const float*)d_in[4];
    float* out = (float*)d_out;
    float* kv  = out + OUT_ELEMS;   // `present` tail of the flattened output

    cudaFuncSetAttribute(attn_k, cudaFuncAttributeMaxDynamicSharedMemorySize, ATTN_SMEM_BYTES);
    cudaFuncSetAttribute(gemm_mma<0>, cudaFuncAttributeMaxDynamicSharedMemorySize, GEMM_SMEM);
    cudaFuncSetAttribute(gemm_mma<1>, cudaFuncAttributeMaxDynamicSharedMemorySize, GEMM_SMEM);

    __nv_bfloat16 *xhat, *ahat, *wat, *wpt;
    cudaGetSymbolAddress((void**)&xhat, g_xhat);
    cudaGetSymbolAddress((void**)&ahat, g_ahat);
    cudaGetSymbolAddress((void**)&wat,  g_wat);
    cudaGetSymbolAddress((void**)&wpt,  g_wpt);

    // 1) split conversions of inputs
    convA_k<<<(TOKENS * 1024 + 255) / 256, 256>>>(x, xhat, TOKENS * 1024);
    {
        dim3 blk(32, 32);
        convBt_k<<<dim3(3 * D_MODEL / 32, D_MODEL / 32), blk>>>(w_attn, wat, 3 * D_MODEL);
        convBt_k<<<dim3(D_MODEL / 32, D_MODEL / 32),     blk>>>(w_proj, wpt, D_MODEL);
    }

    // 2) QKV projection: Q -> g_q, K/V -> present tail of d_out
    gemm_mma<1><<<dim3(3 * D_MODEL / 128, TOKENS / 128), 256, GEMM_SMEM>>>(
        xhat, wat, b_attn, nullptr, kv);

    // 3) sliding-window attention (reads KV from out tail) -> g_ahat (split bf16)
    attn_k<<<BATCH * NH * (S_LEN / 64), 256, ATTN_SMEM_BYTES>>>(kv);

    // 4) output projection -> d_out head
    gemm_mma<0><<<dim3(D_MODEL / 128, TOKENS / 128), 256, GEMM_SMEM>>>(
        ahat, wpt, b_proj, out, nullptr);
}

// round 8
// speedup vs baseline: 1.2090x; 1.0720x over previous
#include <cuda_runtime.h>
#include <cuda_bf16.h>
#include <cstdint>

// Problem constants
#define BATCH   2
#define S_LEN   2048
#define D_MODEL 1024
#define NH      16
#define HD      64
#define WINDOW  256
#define TOKENS  (BATCH * S_LEN)               // 4096
#define OUT_ELEMS ((size_t)TOKENS * D_MODEL)  // 4194304
#define KEFF    3072                          // 3 * 1024 (hi/hi/lo split along K)
#define NCHUNK  48                            // KEFF / 64

// ---------------- device scratch (allocation-free rule) ----------------
__device__ __align__(128) float g_q [BATCH * NH * S_LEN * HD];
__device__ __align__(128) __nv_bfloat16 g_xhat[(size_t)TOKENS * KEFF];      // [A_hi|A_hi|A_lo]
__device__ __align__(128) __nv_bfloat16 g_ahat[(size_t)TOKENS * KEFF];
__device__ __align__(128) __nv_bfloat16 g_wat [(size_t)3 * D_MODEL * KEFF]; // W^T split [B_hi|B_lo|B_hi]
__device__ __align__(128) __nv_bfloat16 g_wpt [(size_t)D_MODEL * KEFF];

// ---------------- helpers ----------------
__device__ __forceinline__ uint32_t smem_u32(const void* p) {
    uint32_t a;
    asm("{ .reg .u64 t; cvta.to.shared.u64 t, %1; cvt.u32.u64 %0, t; }" : "=r"(a) : "l"(p));
    return a;
}
__device__ __forceinline__ void cp16(uint32_t saddr, const void* g) {
    asm volatile("cp.async.cg.shared.global [%0], [%1], 16;" :: "r"(saddr), "l"(g));
}
#define CP_COMMIT() asm volatile("cp.async.commit_group;" ::: "memory")
#define CP_WAIT1()  asm volatile("cp.async.wait_group 1;" ::: "memory")
#define CP_WAIT0()  asm volatile("cp.async.wait_group 0;" ::: "memory")

__device__ __forceinline__ void ldmx4(uint32_t* r, uint32_t addr) {
    asm volatile("ldmatrix.sync.aligned.m8n8.x4.shared.b16 {%0,%1,%2,%3}, [%4];"
                 : "=r"(r[0]), "=r"(r[1]), "=r"(r[2]), "=r"(r[3]) : "r"(addr));
}
__device__ __forceinline__ void mma16816(float* c, const uint32_t* a, const uint32_t* b) {
    asm volatile(
        "mma.sync.aligned.m16n8k16.row.col.f32.bf16.bf16.f32 "
        "{%0,%1,%2,%3}, {%4,%5,%6,%7}, {%8,%9}, {%0,%1,%2,%3};"
        : "+f"(c[0]), "+f"(c[1]), "+f"(c[2]), "+f"(c[3])
        : "r"(a[0]), "r"(a[1]), "r"(a[2]), "r"(a[3]), "r"(b[0]), "r"(b[1]));
}

// ---------------- split conversion kernels ----------------
// fp32 [M,1024] -> bf16 [M,3072] segments [hi | hi | lo]
__global__ void convA_k(const float* __restrict__ A, __nv_bfloat16* __restrict__ O, int total)
{
    int idx = blockIdx.x * blockDim.x + threadIdx.x;
    if (idx >= total) return;
    int m = idx >> 10, k = idx & 1023;
    float v = A[idx];
    __nv_bfloat16 hi = __float2bfloat16(v);
    __nv_bfloat16 lo = __float2bfloat16(v - __bfloat162float(hi));
    __nv_bfloat16* row = O + (size_t)m * KEFF;
    row[k] = hi; row[1024 + k] = hi; row[2048 + k] = lo;
}
// W fp32 [1024, N] row-major -> Bt bf16 [N, 3072] segments [hi | lo | hi] (transpose)
__global__ void convBt_k(const float* __restrict__ W, __nv_bfloat16* __restrict__ O, int N)
{
    __shared__ float tile[32][33];
    int k0 = blockIdx.y * 32, n0 = blockIdx.x * 32;
    int tx = threadIdx.x, ty = threadIdx.y;
    tile[ty][tx] = W[(size_t)(k0 + ty) * N + n0 + tx];
    __syncthreads();
    float v = tile[tx][ty];
    __nv_bfloat16 hi = __float2bfloat16(v);
    __nv_bfloat16 lo = __float2bfloat16(v - __bfloat162float(hi));
    __nv_bfloat16* row = O + (size_t)(n0 + ty) * KEFF;
    int k = k0 + tx;
    row[k] = hi; row[1024 + k] = lo; row[2048 + k] = hi;
}

// ---------------- mma.sync GEMM (unchanged from R7 winner) ----------------
#define TILE_BYTES  18432         // 128 rows * 144B
#define BUF_BYTES   36864         // A + B
#define GEMM_SMEM   110592        // 3 buffers (2 CTAs/SM)

template<int MODE>
__global__ __launch_bounds__(256, 2) void gemm_mma(const __nv_bfloat16* __restrict__ A,
                                                   const __nv_bfloat16* __restrict__ Bt,
                                                   const float* __restrict__ bias,
                                                   float* __restrict__ C,
                                                   float* __restrict__ KV)
{
    extern __shared__ char smem[];
    const uint32_t sb = smem_u32(smem);
    const int tid = threadIdx.x;
    const int wid = tid >> 5, lid = tid & 31;
    const int m0 = blockIdx.y * 128, n0 = blockIdx.x * 128;
    const int mbase = (wid & 1) * 64;
    const int nbase = (wid >> 1) * 32;

    const char* Abase = (const char*)(A  + (size_t)m0 * KEFF);
    const char* Bbase = (const char*)(Bt + (size_t)n0 * KEFF);

    const uint32_t a_row_off = (uint32_t)((mbase + ((lid >> 3) & 1) * 8 + (lid & 7)) * 144
                                          + ((lid >> 4) * 8) * 2);
    const uint32_t b_row_off = (uint32_t)((nbase + ((lid >> 4) & 1) * 8 + (lid & 7)) * 144
                                          + (((lid >> 3) & 1) * 8) * 2);

    float acc[4][4][4];
#pragma unroll
    for (int mt = 0; mt < 4; mt++)
#pragma unroll
        for (int nt = 0; nt < 4; nt++)
#pragma unroll
            for (int i = 0; i < 4; i++) acc[mt][nt][i] = 0.f;

#define PREFETCH(c, buf)                                                          \
    {                                                                             \
        const size_t kbyte = (size_t)(c) * 128;                                   \
        const uint32_t abuf = sb + (buf) * BUF_BYTES;                             \
        const uint32_t bbuf = abuf + TILE_BYTES;                                  \
        _Pragma("unroll")                                                         \
        for (int i = 0; i < 4; i++) {                                             \
            int idx = tid + i * 256;                                              \
            int row = idx >> 3, seg = idx & 7;                                    \
            uint32_t so = row * 144 + seg * 16;                                   \
            cp16(abuf + so, Abase + (size_t)row * (KEFF * 2) + kbyte + seg * 16); \
            cp16(bbuf + so, Bbase + (size_t)row * (KEFF * 2) + kbyte + seg * 16); \
        }                                                                         \
    }

    PREFETCH(0, 0); CP_COMMIT();
    PREFETCH(1, 1); CP_COMMIT();

    int buf = 0;
    for (int c = 0; c < NCHUNK; c++) {
        if (c == NCHUNK - 1) { CP_WAIT0(); } else { CP_WAIT1(); }
        __syncthreads();
        if (c + 2 < NCHUNK) {
            int nbuf = buf + 2; if (nbuf >= 3) nbuf -= 3;
            PREFETCH(c + 2, nbuf);
            CP_COMMIT();
        }
        const uint32_t abuf = sb + buf * BUF_BYTES;
        const uint32_t bbuf = abuf + TILE_BYTES;
#pragma unroll
        for (int ks = 0; ks < 4; ks++) {
            const uint32_t kb = (uint32_t)ks * 32;
            uint32_t ar[4][4];
            uint32_t br[4][2];
#pragma unroll
            for (int mt = 0; mt < 4; mt++)
                ldmx4(ar[mt], abuf + a_row_off + mt * (16 * 144) + kb);
#pragma unroll
            for (int p = 0; p < 2; p++) {
                uint32_t r[4];
                ldmx4(r, bbuf + b_row_off + p * (16 * 144) + kb);
                br[p * 2][0] = r[0]; br[p * 2][1] = r[1];
                br[p * 2 + 1][0] = r[2]; br[p * 2 + 1][1] = r[3];
            }
#pragma unroll
            for (int mt = 0; mt < 4; mt++)
#pragma unroll
                for (int nt = 0; nt < 4; nt++)
                    mma16816(acc[mt][nt], ar[mt], br[nt]);
        }
        if (++buf == 3) buf = 0;
    }
#undef PREFETCH

    const int lrow = lid >> 2;
    const int lcol = (lid & 3) * 2;
#pragma unroll
    for (int mt = 0; mt < 4; mt++) {
        const int gm = m0 + mbase + mt * 16 + lrow;
#pragma unroll
        for (int nt = 0; nt < 4; nt++) {
            const int gn = n0 + nbase + nt * 8 + lcol;
            if (MODE == 0) {
                const float b0 = bias[gn], b1 = bias[gn + 1];
                float2 v0 = {acc[mt][nt][0] + b0, acc[mt][nt][1] + b1};
                float2 v1 = {acc[mt][nt][2] + b0, acc[mt][nt][3] + b1};
                *(float2*)&C[(size_t)gm * D_MODEL + gn] = v0;
                *(float2*)&C[(size_t)(gm + 8) * D_MODEL + gn] = v1;
            } else {
#pragma unroll
                for (int e = 0; e < 4; e++) {
                    const int row = gm + (e >> 1) * 8;
                    const int f   = gn + (e & 1);
                    const float v = acc[mt][nt][e] + bias[f];
                    const int bb = row >> 11, s = row & 2047;
                    const int sec = f >> 10, fr = f & 1023;
                    const int h = fr >> 6, dd = fr & 63;
                    if (sec == 0)
                        g_q[(((size_t)bb * NH + h) * S_LEN + s) * HD + dd] = v;
                    else
                        KV[((((size_t)bb * 2 + (sec - 1)) * NH + h) * S_LEN + s) * HD + dd] = v;
                }
            }
        }
    }
}

// ---------------- flash-style sliding-window attention ----------------
// Online softmax over 5 key tiles; smem = Q/K/V/S tiles only (65 KB) -> 3 CTAs/SM.
// Writes split bf16 directly into g_ahat (fused convA).
#define ATTN_SMEM_BYTES (4 * 64 * 65 * 4)   // 66560

__global__ __launch_bounds__(256, 3) void attn_k(const float* __restrict__ KV)
{
    extern __shared__ float sm[];
    float (*Qs)[65] = (float(*)[65])sm;                 // 64 x 64 Q (scaled)
    float (*Ks)[65] = (float(*)[65])(sm + 64 * 65);     // 64 x 64 K tile
    float (*Vs)[65] = (float(*)[65])(sm + 2 * 64 * 65); // 64 x 64 V tile
    float (*Ps)[65] = (float(*)[65])(sm + 3 * 64 * 65); // 64 x 64 P tile

    const int bid = blockIdx.x;
    const int qt = bid & 31;
    const int h  = (bid >> 5) & 15;
    const int b  = bid >> 9;
    const int qs = qt * 64;

    const int tid = threadIdx.x;
    const int tx = tid & 15;
    const int ty = tid >> 4;
    const int i0 = ty * 4;        // query rows owned by this thread
    const int j0 = tx * 4;        // key cols (score phase) / head dims (PV phase)
    const float scale = 0.125f;   // 1/sqrt(64)

    const float* Qg = g_q + (((size_t)b * NH + h) * S_LEN) * HD;
    const float* Kg = KV + ((((size_t)b * 2 + 0) * NH + h) * S_LEN) * HD;
    const float* Vg = KV + ((((size_t)b * 2 + 1) * NH + h) * S_LEN) * HD;

    // load Q tile (pre-scaled)
    for (int idx = tid; idx < 64 * 64; idx += 256) {
        const int i = idx >> 6, d = idx & 63;
        Qs[i][d] = Qg[(size_t)(qs + i) * HD + d] * scale;
    }

    // running stats & output accumulator (replicated across the 16 tx threads
    // of each row group via shfl all-reduce)
    float m_run[4], rsum[4], o[4][4];
#pragma unroll
    for (int r = 0; r < 4; r++) {
        m_run[r] = -1e29f;  // > mask sentinel (-1e30) so all-masked tiles stay inert
        rsum[r] = 0.f;
#pragma unroll
        for (int c = 0; c < 4; c++) o[r][c] = 0.f;
    }

    for (int kt = 0; kt < 5; kt++) {
        const int ks = qs - 256 + kt * 64;
        if (ks + 64 <= 0) continue;   // tile entirely before sequence start

        __syncthreads();  // prev PV done with Ks/Vs/Ps; Q visible after 1st barrier
        for (int idx = tid; idx < 64 * 64; idx += 256) {
            const int j = idx >> 6, d = idx & 63;
            const int gj = ks + j;
            const bool in = (gj >= 0);
            Ks[j][d] = in ? Kg[(size_t)gj * HD + d] : 0.f;
            Vs[j][d] = in ? Vg[(size_t)gj * HD + d] : 0.f;
        }
        __syncthreads();

        // ---- scores for this tile ----
        float s[4][4];
#pragma unroll
        for (int r = 0; r < 4; r++)
#pragma unroll
            for (int c = 0; c < 4; c++) s[r][c] = 0.f;
#pragma unroll 8
        for (int d = 0; d < 64; d++) {
            float q[4], kk[4];
#pragma unroll
            for (int r = 0; r < 4; r++) q[r] = Qs[i0 + r][d];
#pragma unroll
            for (int c = 0; c < 4; c++) kk[c] = Ks[j0 + c][d];
#pragma unroll
            for (int r = 0; r < 4; r++)
#pragma unroll
                for (int c = 0; c < 4; c++) s[r][c] += q[r] * kk[c];
        }
        // mask
#pragma unroll
        for (int r = 0; r < 4; r++) {
            const int gi = qs + i0 + r;
#pragma unroll
            for (int c = 0; c < 4; c++) {
                const int gj = ks + j0 + c;
                const bool ok = (gj >= 0) && (gj <= gi) && (gj > gi - WINDOW);
                if (!ok) s[r][c] = -1e30f;
            }
        }

        // ---- per-row tile max (all-reduce over the 16 tx threads) ----
        float tmax[4];
#pragma unroll
        for (int r = 0; r < 4; r++) {
            float m = fmaxf(fmaxf(s[r][0], s[r][1]), fmaxf(s[r][2], s[r][3]));
#pragma unroll
            for (int w = 1; w < 16; w <<= 1)
                m = fmaxf(m, __shfl_xor_sync(0xffffffffu, m, w));
            tmax[r] = m;
        }

        // ---- online softmax update ----
        float rs[4];
#pragma unroll
        for (int r = 0; r < 4; r++) {
            const float m_new = fmaxf(m_run[r], tmax[r]);
            const float alpha = __expf(m_run[r] - m_new);
            float lsum = 0.f;
#pragma unroll
            for (int c = 0; c < 4; c++) {
                const float p = __expf(s[r][c] - m_new);
                Ps[i0 + r][j0 + c] = p;
                lsum += p;
            }
#pragma unroll
            for (int w = 1; w < 16; w <<= 1)
                lsum += __shfl_xor_sync(0xffffffffu, lsum, w);
            rs[r] = lsum;
            rsum[r] = rsum[r] * alpha + lsum;
#pragma unroll
            for (int c = 0; c < 4; c++) o[r][c] *= alpha;
            m_run[r] = m_new;
        }
        (void)rs;
        __syncthreads();  // Ps ready for all threads

        // ---- PV accumulate ----
#pragma unroll 8
        for (int j = 0; j < 64; j++) {
            float p[4], v[4];
#pragma unroll
            for (int r = 0; r < 4; r++) p[r] = Ps[i0 + r][j];
#pragma unroll
            for (int c = 0; c < 4; c++) v[c] = Vs[j][j0 + c];
#pragma unroll
            for (int r = 0; r < 4; r++)
#pragma unroll
                for (int c = 0; c < 4; c++) o[r][c] += p[r] * v[c];
        }
    }

    // fused epilogue: normalize and write hi/hi/lo split bf16 into g_ahat
#pragma unroll
    for (int r = 0; r < 4; r++) {
        const float ri = 1.f / rsum[r];
        const size_t m = (size_t)b * S_LEN + qs + i0 + r;
        __nv_bfloat16* row = g_ahat + m * KEFF;
        const int k = h * HD + j0;
#pragma unroll
        for (int c = 0; c < 4; c++) {
            const float v = o[r][c] * ri;
            const __nv_bfloat16 hi = __float2bfloat16(v);
            const __nv_bfloat16 lo = __float2bfloat16(v - __bfloat162float(hi));
            row[k + c] = hi;
            row[1024 + k + c] = hi;
            row[2048 + k + c] = lo;
        }
    }
}

// ---------------------------------------------------------------------------
extern "C" void kernel_launch(void* const* d_in, const int* in_sizes, int n_in,
                              void* d_out, int out_size)
{
    const float* x      = (const float*)d_in[0];
    const float* w_attn = (const float*)d_in[1];
    const float* b_attn = (const float*)d_in[2];
    const float* w_proj = (const float*)d_in[3];
    const float* b_proj = (const float*)d_in[4];
    float* out = (float*)d_out;
    float* kv  = out + OUT_ELEMS;   // `present` tail of the flattened output

    cudaFuncSetAttribute(attn_k, cudaFuncAttributeMaxDynamicSharedMemorySize, ATTN_SMEM_BYTES);
    cudaFuncSetAttribute(gemm_mma<0>, cudaFuncAttributeMaxDynamicSharedMemorySize, GEMM_SMEM);
    cudaFuncSetAttribute(gemm_mma<1>, cudaFuncAttributeMaxDynamicSharedMemorySize, GEMM_SMEM);

    __nv_bfloat16 *xhat, *ahat, *wat, *wpt;
    cudaGetSymbolAddress((void**)&xhat, g_xhat);
    cudaGetSymbolAddress((void**)&ahat, g_ahat);
    cudaGetSymbolAddress((void**)&wat,  g_wat);
    cudaGetSymbolAddress((void**)&wpt,  g_wpt);

    // 1) split conversions of inputs
    convA_k<<<(TOKENS * 1024 + 255) / 256, 256>>>(x, xhat, TOKENS * 1024);
    {
        dim3 blk(32, 32);
        convBt_k<<<dim3(3 * D_MODEL / 32, D_MODEL / 32), blk>>>(w_attn, wat, 3 * D_MODEL);
        convBt_k<<<dim3(D_MODEL / 32, D_MODEL / 32),     blk>>>(w_proj, wpt, D_MODEL);
    }

    // 2) QKV projection: Q -> g_q, K/V -> present tail of d_out
    gemm_mma<1><<<dim3(3 * D_MODEL / 128, TOKENS / 128), 256, GEMM_SMEM>>>(
        xhat, wat, b_attn, nullptr, kv);

    // 3) flash sliding-window attention (reads KV from out tail) -> g_ahat
    attn_k<<<BATCH * NH * (S_LEN / 64), 256, ATTN_SMEM_BYTES>>>(kv);

    // 4) output projection -> d_out head
    gemm_mma<0><<<dim3(D_MODEL / 128, TOKENS / 128), 256, GEMM_SMEM>>>(
        ahat, wpt, b_proj, out, nullptr);
}

// round 9
// speedup vs baseline: 1.2307x; 1.0179x over previous
#include <cuda_runtime.h>
#include <cuda_bf16.h>
#include <cstdint>

// Problem constants
#define BATCH   2
#define S_LEN   2048
#define D_MODEL 1024
#define NH      16
#define HD      64
#define WINDOW  256
#define TOKENS  (BATCH * S_LEN)               // 4096
#define OUT_ELEMS ((size_t)TOKENS * D_MODEL)  // 4194304
#define KEFF    3072                          // 3 * 1024 (hi/hi/lo split along K)
#define NCHUNK  48                            // KEFF / 64

// ---------------- device scratch (allocation-free rule) ----------------
__device__ __align__(128) float g_q [BATCH * NH * S_LEN * HD];
__device__ __align__(128) __nv_bfloat16 g_xhat[(size_t)TOKENS * KEFF];      // [A_hi|A_hi|A_lo]
__device__ __align__(128) __nv_bfloat16 g_ahat[(size_t)TOKENS * KEFF];
__device__ __align__(128) __nv_bfloat16 g_wat [(size_t)3 * D_MODEL * KEFF]; // W^T split [B_hi|B_lo|B_hi]
__device__ __align__(128) __nv_bfloat16 g_wpt [(size_t)D_MODEL * KEFF];

// ---------------- helpers ----------------
__device__ __forceinline__ uint32_t smem_u32(const void* p) {
    uint32_t a;
    asm("{ .reg .u64 t; cvta.to.shared.u64 t, %1; cvt.u32.u64 %0, t; }" : "=r"(a) : "l"(p));
    return a;
}
__device__ __forceinline__ void cp16(uint32_t saddr, const void* g) {
    asm volatile("cp.async.cg.shared.global [%0], [%1], 16;" :: "r"(saddr), "l"(g));
}
#define CP_COMMIT() asm volatile("cp.async.commit_group;" ::: "memory")
#define CP_WAIT1()  asm volatile("cp.async.wait_group 1;" ::: "memory")
#define CP_WAIT0()  asm volatile("cp.async.wait_group 0;" ::: "memory")

__device__ __forceinline__ void ldmx4(uint32_t* r, uint32_t addr) {
    asm volatile("ldmatrix.sync.aligned.m8n8.x4.shared.b16 {%0,%1,%2,%3}, [%4];"
                 : "=r"(r[0]), "=r"(r[1]), "=r"(r[2]), "=r"(r[3]) : "r"(addr));
}
__device__ __forceinline__ void mma16816(float* c, const uint32_t* a, const uint32_t* b) {
    asm volatile(
        "mma.sync.aligned.m16n8k16.row.col.f32.bf16.bf16.f32 "
        "{%0,%1,%2,%3}, {%4,%5,%6,%7}, {%8,%9}, {%0,%1,%2,%3};"
        : "+f"(c[0]), "+f"(c[1]), "+f"(c[2]), "+f"(c[3])
        : "r"(a[0]), "r"(a[1]), "r"(a[2]), "r"(a[3]), "r"(b[0]), "r"(b[1]));
}

// ---------------- split conversion kernels ----------------
__global__ void convA_k(const float* __restrict__ A, __nv_bfloat16* __restrict__ O, int total)
{
    int idx = blockIdx.x * blockDim.x + threadIdx.x;
    if (idx >= total) return;
    int m = idx >> 10, k = idx & 1023;
    float v = A[idx];
    __nv_bfloat16 hi = __float2bfloat16(v);
    __nv_bfloat16 lo = __float2bfloat16(v - __bfloat162float(hi));
    __nv_bfloat16* row = O + (size_t)m * KEFF;
    row[k] = hi; row[1024 + k] = hi; row[2048 + k] = lo;
}
__global__ void convBt_k(const float* __restrict__ W, __nv_bfloat16* __restrict__ O, int N)
{
    __shared__ float tile[32][33];
    int k0 = blockIdx.y * 32, n0 = blockIdx.x * 32;
    int tx = threadIdx.x, ty = threadIdx.y;
    tile[ty][tx] = W[(size_t)(k0 + ty) * N + n0 + tx];
    __syncthreads();
    float v = tile[tx][ty];
    __nv_bfloat16 hi = __float2bfloat16(v);
    __nv_bfloat16 lo = __float2bfloat16(v - __bfloat162float(hi));
    __nv_bfloat16* row = O + (size_t)(n0 + ty) * KEFF;
    int k = k0 + tx;
    row[k] = hi; row[1024 + k] = lo; row[2048 + k] = hi;
}

// ---------------- mma.sync GEMM (unchanged from R7/R8 winner) ----------------
#define TILE_BYTES  18432
#define BUF_BYTES   36864
#define GEMM_SMEM   110592

template<int MODE>
__global__ __launch_bounds__(256, 2) void gemm_mma(const __nv_bfloat16* __restrict__ A,
                                                   const __nv_bfloat16* __restrict__ Bt,
                                                   const float* __restrict__ bias,
                                                   float* __restrict__ C,
                                                   float* __restrict__ KV)
{
    extern __shared__ char smem[];
    const uint32_t sb = smem_u32(smem);
    const int tid = threadIdx.x;
    const int wid = tid >> 5, lid = tid & 31;
    const int m0 = blockIdx.y * 128, n0 = blockIdx.x * 128;
    const int mbase = (wid & 1) * 64;
    const int nbase = (wid >> 1) * 32;

    const char* Abase = (const char*)(A  + (size_t)m0 * KEFF);
    const char* Bbase = (const char*)(Bt + (size_t)n0 * KEFF);

    const uint32_t a_row_off = (uint32_t)((mbase + ((lid >> 3) & 1) * 8 + (lid & 7)) * 144
                                          + ((lid >> 4) * 8) * 2);
    const uint32_t b_row_off = (uint32_t)((nbase + ((lid >> 4) & 1) * 8 + (lid & 7)) * 144
                                          + (((lid >> 3) & 1) * 8) * 2);

    float acc[4][4][4];
#pragma unroll
    for (int mt = 0; mt < 4; mt++)
#pragma unroll
        for (int nt = 0; nt < 4; nt++)
#pragma unroll
            for (int i = 0; i < 4; i++) acc[mt][nt][i] = 0.f;

#define PREFETCH(c, buf)                                                          \
    {                                                                             \
        const size_t kbyte = (size_t)(c) * 128;                                   \
        const uint32_t abuf = sb + (buf) * BUF_BYTES;                             \
        const uint32_t bbuf = abuf + TILE_BYTES;                                  \
        _Pragma("unroll")                                                         \
        for (int i = 0; i < 4; i++) {                                             \
            int idx = tid + i * 256;                                              \
            int row = idx >> 3, seg = idx & 7;                                    \
            uint32_t so = row * 144 + seg * 16;                                   \
            cp16(abuf + so, Abase + (size_t)row * (KEFF * 2) + kbyte + seg * 16); \
            cp16(bbuf + so, Bbase + (size_t)row * (KEFF * 2) + kbyte + seg * 16); \
        }                                                                         \
    }

    PREFETCH(0, 0); CP_COMMIT();
    PREFETCH(1, 1); CP_COMMIT();

    int buf = 0;
    for (int c = 0; c < NCHUNK; c++) {
        if (c == NCHUNK - 1) { CP_WAIT0(); } else { CP_WAIT1(); }
        __syncthreads();
        if (c + 2 < NCHUNK) {
            int nbuf = buf + 2; if (nbuf >= 3) nbuf -= 3;
            PREFETCH(c + 2, nbuf);
            CP_COMMIT();
        }
        const uint32_t abuf = sb + buf * BUF_BYTES;
        const uint32_t bbuf = abuf + TILE_BYTES;
#pragma unroll
        for (int ks = 0; ks < 4; ks++) {
            const uint32_t kb = (uint32_t)ks * 32;
            uint32_t ar[4][4];
            uint32_t br[4][2];
#pragma unroll
            for (int mt = 0; mt < 4; mt++)
                ldmx4(ar[mt], abuf + a_row_off + mt * (16 * 144) + kb);
#pragma unroll
            for (int p = 0; p < 2; p++) {
                uint32_t r[4];
                ldmx4(r, bbuf + b_row_off + p * (16 * 144) + kb);
                br[p * 2][0] = r[0]; br[p * 2][1] = r[1];
                br[p * 2 + 1][0] = r[2]; br[p * 2 + 1][1] = r[3];
            }
#pragma unroll
            for (int mt = 0; mt < 4; mt++)
#pragma unroll
                for (int nt = 0; nt < 4; nt++)
                    mma16816(acc[mt][nt], ar[mt], br[nt]);
        }
        if (++buf == 3) buf = 0;
    }
#undef PREFETCH

    const int lrow = lid >> 2;
    const int lcol = (lid & 3) * 2;
#pragma unroll
    for (int mt = 0; mt < 4; mt++) {
        const int gm = m0 + mbase + mt * 16 + lrow;
#pragma unroll
        for (int nt = 0; nt < 4; nt++) {
            const int gn = n0 + nbase + nt * 8 + lcol;
            if (MODE == 0) {
                const float b0 = bias[gn], b1 = bias[gn + 1];
                float2 v0 = {acc[mt][nt][0] + b0, acc[mt][nt][1] + b1};
                float2 v1 = {acc[mt][nt][2] + b0, acc[mt][nt][3] + b1};
                *(float2*)&C[(size_t)gm * D_MODEL + gn] = v0;
                *(float2*)&C[(size_t)(gm + 8) * D_MODEL + gn] = v1;
            } else {
#pragma unroll
                for (int e = 0; e < 4; e++) {
                    const int row = gm + (e >> 1) * 8;
                    const int f   = gn + (e & 1);
                    const float v = acc[mt][nt][e] + bias[f];
                    const int bb = row >> 11, s = row & 2047;
                    const int sec = f >> 10, fr = f & 1023;
                    const int h = fr >> 6, dd = fr & 63;
                    if (sec == 0)
                        g_q[(((size_t)bb * NH + h) * S_LEN + s) * HD + dd] = v;
                    else
                        KV[((((size_t)bb * 2 + (sec - 1)) * NH + h) * S_LEN + s) * HD + dd] = v;
                }
            }
        }
    }
}

// ---------------- flash attention, float4 smem with XOR chunk swizzle ----------------
// K/V/P tiles: 64x64 f32, chunk c (float4) of row r stored at c ^ ((r>>2)&7).
// Q tile linear (reads are broadcast). Smem 64 KB -> 3 CTAs/SM.
#define ATTN_SMEM_BYTES 65536

__global__ __launch_bounds__(256, 3) void attn_k(const float* __restrict__ KV)
{
    extern __shared__ float sm[];
    float* Qs = sm;                 // [64][64] linear
    float* Ks = sm + 4096;          // [64][64] swizzled
    float* Vs = sm + 8192;          // [64][64] swizzled
    float* Ps = sm + 12288;         // [64][64] swizzled

    const int bid = blockIdx.x;
    const int qt = bid & 31;
    const int h  = (bid >> 5) & 15;
    const int b  = bid >> 9;
    const int qs = qt * 64;

    const int tid = threadIdx.x;
    const int tx = tid & 15;        // 0..15: key cols / head dims (x4)
    const int ty = tid >> 4;        // 0..15: query rows (x4)
    const int i0 = ty * 4;
    const int j0 = tx * 4;
    const int sQ = ty & 7;          // swizzle const for this thread's P/Q rows
    const int sK = tx & 7;          // swizzle const for this thread's K rows
    const float scale = 0.125f;

    const float* Qg = g_q + (((size_t)b * NH + h) * S_LEN) * HD;
    const float* Kg = KV + ((((size_t)b * 2 + 0) * NH + h) * S_LEN) * HD;
    const float* Vg = KV + ((((size_t)b * 2 + 1) * NH + h) * S_LEN) * HD;

    // load Q tile (pre-scaled), float4, linear layout
    for (int idx = tid; idx < 1024; idx += 256) {
        const int i = idx >> 4, dc = idx & 15;
        float4 v = *(const float4*)&Qg[(size_t)(qs + i) * HD + dc * 4];
        v.x *= scale; v.y *= scale; v.z *= scale; v.w *= scale;
        *(float4*)&Qs[i * 64 + dc * 4] = v;
    }

    float m_run[4], rsum[4], o[4][4];
#pragma unroll
    for (int r = 0; r < 4; r++) {
        m_run[r] = -1e29f;
        rsum[r] = 0.f;
#pragma unroll
        for (int c = 0; c < 4; c++) o[r][c] = 0.f;
    }

    for (int kt = 0; kt < 5; kt++) {
        const int ks = qs - 256 + kt * 64;
        if (ks + 64 <= 0) continue;

        __syncthreads();   // prev PV done with Ks/Vs/Ps; Q visible
        // load K/V tiles, float4, swizzled: chunk cc of row j -> cc ^ ((j>>2)&7)
        for (int idx = tid; idx < 1024; idx += 256) {
            const int j = idx >> 4, cc = idx & 15;
            const int gj = ks + j;
            const int pc = cc ^ ((j >> 2) & 7);
            float4 kv;
            if (gj >= 0) {
                kv = *(const float4*)&Kg[(size_t)gj * HD + cc * 4];
                *(float4*)&Ks[j * 64 + pc * 4] = kv;
                kv = *(const float4*)&Vg[(size_t)gj * HD + cc * 4];
                *(float4*)&Vs[j * 64 + pc * 4] = kv;
            } else {
                kv = make_float4(0.f, 0.f, 0.f, 0.f);
                *(float4*)&Ks[j * 64 + pc * 4] = kv;
                *(float4*)&Vs[j * 64 + pc * 4] = kv;
            }
        }
        __syncthreads();

        // ---- scores: s[r][c] = sum_d Q[i0+r][d] * K[j0+c][d] ----
        float s[4][4];
#pragma unroll
        for (int r = 0; r < 4; r++)
#pragma unroll
            for (int c = 0; c < 4; c++) s[r][c] = 0.f;
#pragma unroll 4
        for (int dc = 0; dc < 16; dc++) {
            float4 q[4], k[4];
#pragma unroll
            for (int r = 0; r < 4; r++)
                q[r] = *(const float4*)&Qs[(i0 + r) * 64 + dc * 4];
#pragma unroll
            for (int c = 0; c < 4; c++)
                k[c] = *(const float4*)&Ks[(j0 + c) * 64 + (dc ^ sK) * 4];
#pragma unroll
            for (int r = 0; r < 4; r++)
#pragma unroll
                for (int c = 0; c < 4; c++)
                    s[r][c] += q[r].x * k[c].x + q[r].y * k[c].y
                             + q[r].z * k[c].z + q[r].w * k[c].w;
        }
        // mask
#pragma unroll
        for (int r = 0; r < 4; r++) {
            const int gi = qs + i0 + r;
#pragma unroll
            for (int c = 0; c < 4; c++) {
                const int gj = ks + j0 + c;
                const bool ok = (gj >= 0) && (gj <= gi) && (gj > gi - WINDOW);
                if (!ok) s[r][c] = -1e30f;
            }
        }

        // ---- per-row tile max (all-reduce over 16 tx lanes) ----
        float tmax[4];
#pragma unroll
        for (int r = 0; r < 4; r++) {
            float m = fmaxf(fmaxf(s[r][0], s[r][1]), fmaxf(s[r][2], s[r][3]));
#pragma unroll
            for (int w = 1; w < 16; w <<= 1)
                m = fmaxf(m, __shfl_xor_sync(0xffffffffu, m, w));
            tmax[r] = m;
        }

        // ---- online softmax update; P -> swizzled smem ----
#pragma unroll
        for (int r = 0; r < 4; r++) {
            const float m_new = fmaxf(m_run[r], tmax[r]);
            const float alpha = __expf(m_run[r] - m_new);
            float lsum = 0.f;
            float* prow = Ps + (i0 + r) * 64 + (tx ^ sQ) * 4;  // chunk tx of row i0+r
#pragma unroll
            for (int c = 0; c < 4; c++) {
                const float p = __expf(s[r][c] - m_new);
                prow[c] = p;
                lsum += p;
            }
#pragma unroll
            for (int w = 1; w < 16; w <<= 1)
                lsum += __shfl_xor_sync(0xffffffffu, lsum, w);
            rsum[r] = rsum[r] * alpha + lsum;
#pragma unroll
            for (int c = 0; c < 4; c++) o[r][c] *= alpha;
            m_run[r] = m_new;
        }
        __syncthreads();  // Ps ready

        // ---- PV: o[r][c] += sum_j P[i0+r][j] * V[j][j0+c] ----
#pragma unroll 4
        for (int jc = 0; jc < 16; jc++) {
            float4 p[4], v[4];
#pragma unroll
            for (int r = 0; r < 4; r++)
                p[r] = *(const float4*)&Ps[(i0 + r) * 64 + (jc ^ sQ) * 4];
#pragma unroll
            for (int jj = 0; jj < 4; jj++)
                v[jj] = *(const float4*)&Vs[(jc * 4 + jj) * 64 + (tx ^ (jc & 7)) * 4];
#pragma unroll
            for (int r = 0; r < 4; r++) {
                o[r][0] += p[r].x * v[0].x + p[r].y * v[1].x + p[r].z * v[2].x + p[r].w * v[3].x;
                o[r][1] += p[r].x * v[0].y + p[r].y * v[1].y + p[r].z * v[2].y + p[r].w * v[3].y;
                o[r][2] += p[r].x * v[0].z + p[r].y * v[1].z + p[r].z * v[2].z + p[r].w * v[3].z;
                o[r][3] += p[r].x * v[0].w + p[r].y * v[1].w + p[r].z * v[2].w + p[r].w * v[3].w;
            }
        }
    }

    // fused epilogue: normalize, hi/hi/lo split bf16 into g_ahat
#pragma unroll
    for (int r = 0; r < 4; r++) {
        const float ri = 1.f / rsum[r];
        const size_t m = (size_t)b * S_LEN + qs + i0 + r;
        __nv_bfloat16* row = g_ahat + m * KEFF;
        const int k = h * HD + j0;
#pragma unroll
        for (int c = 0; c < 4; c++) {
            const float v = o[r][c] * ri;
            const __nv_bfloat16 hi = __float2bfloat16(v);
            const __nv_bfloat16 lo = __float2bfloat16(v - __bfloat162float(hi));
            row[k + c] = hi;
            row[1024 + k + c] = hi;
            row[2048 + k + c] = lo;
        }
    }
}

// ---------------------------------------------------------------------------
extern "C" void kernel_launch(void* const* d_in, const int* in_sizes, int n_in,
                              void* d_out, int out_size)
{
    const float* x      = (const float*)d_in[0];
    const float* w_attn = (const float*)d_in[1];
    const float* b_attn = (const float*)d_in[2];
    const float* w_proj = (const float*)d_in[3];
    const float* b_proj = (const float*)d_in[4];
    float* out = (float*)d_out;
    float* kv  = out + OUT_ELEMS;

    cudaFuncSetAttribute(attn_k, cudaFuncAttributeMaxDynamicSharedMemorySize, ATTN_SMEM_BYTES);
    cudaFuncSetAttribute(gemm_mma<0>, cudaFuncAttributeMaxDynamicSharedMemorySize, GEMM_SMEM);
    cudaFuncSetAttribute(gemm_mma<1>, cudaFuncAttributeMaxDynamicSharedMemorySize, GEMM_SMEM);

    __nv_bfloat16 *xhat, *ahat, *wat, *wpt;
    cudaGetSymbolAddress((void**)&xhat, g_xhat);
    cudaGetSymbolAddress((void**)&ahat, g_ahat);
    cudaGetSymbolAddress((void**)&wat,  g_wat);
    cudaGetSymbolAddress((void**)&wpt,  g_wpt);

    // 1) split conversions of inputs
    convA_k<<<(TOKENS * 1024 + 255) / 256, 256>>>(x, xhat, TOKENS * 1024);
    {
        dim3 blk(32, 32);
        convBt_k<<<dim3(3 * D_MODEL / 32, D_MODEL / 32), blk>>>(w_attn, wat, 3 * D_MODEL);
        convBt_k<<<dim3(D_MODEL / 32, D_MODEL / 32),     blk>>>(w_proj, wpt, D_MODEL);
    }

    // 2) QKV projection: Q -> g_q, K/V -> present tail of d_out
    gemm_mma<1><<<dim3(3 * D_MODEL / 128, TOKENS / 128), 256, GEMM_SMEM>>>(
        xhat, wat, b_attn, nullptr, kv);

    // 3) flash sliding-window attention -> g_ahat (split bf16)
    attn_k<<<BATCH * NH * (S_LEN / 64), 256, ATTN_SMEM_BYTES>>>(kv);

    // 4) output projection -> d_out head
    gemm_mma<0><<<dim3(D_MODEL / 128, TOKENS / 128), 256, GEMM_SMEM>>>(
        ahat, wpt, b_proj, out, nullptr);
}

// round 10
// speedup vs baseline: 1.2945x; 1.0519x over previous
#include <cuda_runtime.h>
#include <cuda_bf16.h>
#include <cstdint>

// Problem constants
#define BATCH   2
#define S_LEN   2048
#define D_MODEL 1024
#define NH      16
#define HD      64
#define WINDOW  256
#define TOKENS  (BATCH * S_LEN)               // 4096
#define OUT_ELEMS ((size_t)TOKENS * D_MODEL)  // 4194304
#define KEFF    3072                          // 3 * 1024 (hi/hi/lo split along K)
#define NCHUNK  48                            // KEFF / 64

// ---------------- device scratch (allocation-free rule) ----------------
__device__ __align__(128) float g_q [BATCH * NH * S_LEN * HD];
__device__ __align__(128) __nv_bfloat16 g_xhat[(size_t)TOKENS * KEFF];      // [A_hi|A_hi|A_lo]
__device__ __align__(128) __nv_bfloat16 g_ahat[(size_t)TOKENS * KEFF];
__device__ __align__(128) __nv_bfloat16 g_wat [(size_t)3 * D_MODEL * KEFF]; // W^T split [B_hi|B_lo|B_hi]
__device__ __align__(128) __nv_bfloat16 g_wpt [(size_t)D_MODEL * KEFF];

// ---------------- helpers ----------------
__device__ __forceinline__ uint32_t smem_u32(const void* p) {
    uint32_t a;
    asm("{ .reg .u64 t; cvta.to.shared.u64 t, %1; cvt.u32.u64 %0, t; }" : "=r"(a) : "l"(p));
    return a;
}
__device__ __forceinline__ void cp16(uint32_t saddr, const void* g) {
    asm volatile("cp.async.cg.shared.global [%0], [%1], 16;" :: "r"(saddr), "l"(g));
}
#define CP_COMMIT() asm volatile("cp.async.commit_group;" ::: "memory")
#define CP_WAIT1()  asm volatile("cp.async.wait_group 1;" ::: "memory")
#define CP_WAIT0()  asm volatile("cp.async.wait_group 0;" ::: "memory")

__device__ __forceinline__ void ldmx4(uint32_t* r, uint32_t addr) {
    asm volatile("ldmatrix.sync.aligned.m8n8.x4.shared.b16 {%0,%1,%2,%3}, [%4];"
                 : "=r"(r[0]), "=r"(r[1]), "=r"(r[2]), "=r"(r[3]) : "r"(addr));
}
__device__ __forceinline__ void mma16816(float* c, const uint32_t* a, const uint32_t* b) {
    asm volatile(
        "mma.sync.aligned.m16n8k16.row.col.f32.bf16.bf16.f32 "
        "{%0,%1,%2,%3}, {%4,%5,%6,%7}, {%8,%9}, {%0,%1,%2,%3};"
        : "+f"(c[0]), "+f"(c[1]), "+f"(c[2]), "+f"(c[3])
        : "r"(a[0]), "r"(a[1]), "r"(a[2]), "r"(a[3]), "r"(b[0]), "r"(b[1]));
}
// pack two floats to bf16x2 word (x = first arg in low half)
__device__ __forceinline__ uint32_t bf2pack(float a, float b) {
    __nv_bfloat162 t = __floats2bfloat162_rn(a, b);
    return *reinterpret_cast<uint32_t*>(&t);
}

// ---------------- split conversion kernels (vectorized) ----------------
// fp32 [M,1024] -> bf16 [M,3072] segments [hi | hi | lo]; 4 elems/thread
__global__ void convA_k(const float* __restrict__ A, __nv_bfloat16* __restrict__ O, int total4)
{
    int idx = blockIdx.x * blockDim.x + threadIdx.x;
    if (idx >= total4) return;
    const int m = idx >> 8;          // 256 quads per 1024-row
    const int k = (idx & 255) * 4;
    float4 v = *(const float4*)&A[(size_t)m * 1024 + k];
    float h0f, h1f, h2f, h3f;
    __nv_bfloat16 h0 = __float2bfloat16(v.x); h0f = __bfloat162float(h0);
    __nv_bfloat16 h1 = __float2bfloat16(v.y); h1f = __bfloat162float(h1);
    __nv_bfloat16 h2 = __float2bfloat16(v.z); h2f = __bfloat162float(h2);
    __nv_bfloat16 h3 = __float2bfloat16(v.w); h3f = __bfloat162float(h3);
    uint2 H = {bf2pack(v.x, v.y), bf2pack(v.z, v.w)};       // re-round == hi
    uint2 L = {bf2pack(v.x - h0f, v.y - h1f), bf2pack(v.z - h2f, v.w - h3f)};
    __nv_bfloat16* row = O + (size_t)m * KEFF;
    *(uint2*)&row[k]        = H;
    *(uint2*)&row[1024 + k] = H;
    *(uint2*)&row[2048 + k] = L;
}
// W fp32 [1024, N] row-major -> Bt bf16 [N, 3072] segments [hi | lo | hi] (transpose)
// blockDim (8, 32): float4 loads, conflict-free transposed reads, 8B stores.
__global__ void convBt_k(const float* __restrict__ W, __nv_bfloat16* __restrict__ O, int N)
{
    __shared__ float tile[32][33];
    const int k0 = blockIdx.y * 32, n0 = blockIdx.x * 32;
    const int tx = threadIdx.x;   // 0..7
    const int ty = threadIdx.y;   // 0..31
    float4 w4 = *(const float4*)&W[(size_t)(k0 + ty) * N + n0 + tx * 4];
    tile[ty][tx * 4 + 0] = w4.x;
    tile[ty][tx * 4 + 1] = w4.y;
    tile[ty][tx * 4 + 2] = w4.z;
    tile[ty][tx * 4 + 3] = w4.w;
    __syncthreads();
    const int tid = ty * 8 + tx;
    const int nr = tid >> 3;      // 0..31 output n-row
    const int kq = tid & 7;       // 0..7 k-quad
    float v0 = tile[kq * 4 + 0][nr];
    float v1 = tile[kq * 4 + 1][nr];
    float v2 = tile[kq * 4 + 2][nr];
    float v3 = tile[kq * 4 + 3][nr];
    float h0 = __bfloat162float(__float2bfloat16(v0));
    float h1 = __bfloat162float(__float2bfloat16(v1));
    float h2 = __bfloat162float(__float2bfloat16(v2));
    float h3 = __bfloat162float(__float2bfloat16(v3));
    uint2 H = {bf2pack(v0, v1), bf2pack(v2, v3)};
    uint2 L = {bf2pack(v0 - h0, v1 - h1), bf2pack(v2 - h2, v3 - h3)};
    __nv_bfloat16* row = O + (size_t)(n0 + nr) * KEFF;
    const int k = k0 + kq * 4;
    *(uint2*)&row[k]        = H;
    *(uint2*)&row[1024 + k] = L;
    *(uint2*)&row[2048 + k] = H;
}

// ---------------- mma.sync GEMM (R7 winner; MODE-1 epilogue float2) ----------------
#define TILE_BYTES  18432
#define BUF_BYTES   36864
#define GEMM_SMEM   110592

template<int MODE>
__global__ __launch_bounds__(256, 2) void gemm_mma(const __nv_bfloat16* __restrict__ A,
                                                   const __nv_bfloat16* __restrict__ Bt,
                                                   const float* __restrict__ bias,
                                                   float* __restrict__ C,
                                                   float* __restrict__ KV)
{
    extern __shared__ char smem[];
    const uint32_t sb = smem_u32(smem);
    const int tid = threadIdx.x;
    const int wid = tid >> 5, lid = tid & 31;
    const int m0 = blockIdx.y * 128, n0 = blockIdx.x * 128;
    const int mbase = (wid & 1) * 64;
    const int nbase = (wid >> 1) * 32;

    const char* Abase = (const char*)(A  + (size_t)m0 * KEFF);
    const char* Bbase = (const char*)(Bt + (size_t)n0 * KEFF);

    const uint32_t a_row_off = (uint32_t)((mbase + ((lid >> 3) & 1) * 8 + (lid & 7)) * 144
                                          + ((lid >> 4) * 8) * 2);
    const uint32_t b_row_off = (uint32_t)((nbase + ((lid >> 4) & 1) * 8 + (lid & 7)) * 144
                                          + (((lid >> 3) & 1) * 8) * 2);

    float acc[4][4][4];
#pragma unroll
    for (int mt = 0; mt < 4; mt++)
#pragma unroll
        for (int nt = 0; nt < 4; nt++)
#pragma unroll
            for (int i = 0; i < 4; i++) acc[mt][nt][i] = 0.f;

#define PREFETCH(c, buf)                                                          \
    {                                                                             \
        const size_t kbyte = (size_t)(c) * 128;                                   \
        const uint32_t abuf = sb + (buf) * BUF_BYTES;                             \
        const uint32_t bbuf = abuf + TILE_BYTES;                                  \
        _Pragma("unroll")                                                         \
        for (int i = 0; i < 4; i++) {                                             \
            int idx = tid + i * 256;                                              \
            int row = idx >> 3, seg = idx & 7;                                    \
            uint32_t so = row * 144 + seg * 16;                                   \
            cp16(abuf + so, Abase + (size_t)row * (KEFF * 2) + kbyte + seg * 16); \
            cp16(bbuf + so, Bbase + (size_t)row * (KEFF * 2) + kbyte + seg * 16); \
        }                                                                         \
    }

    PREFETCH(0, 0); CP_COMMIT();
    PREFETCH(1, 1); CP_COMMIT();

    int buf = 0;
    for (int c = 0; c < NCHUNK; c++) {
        if (c == NCHUNK - 1) { CP_WAIT0(); } else { CP_WAIT1(); }
        __syncthreads();
        if (c + 2 < NCHUNK) {
            int nbuf = buf + 2; if (nbuf >= 3) nbuf -= 3;
            PREFETCH(c + 2, nbuf);
            CP_COMMIT();
        }
        const uint32_t abuf = sb + buf * BUF_BYTES;
        const uint32_t bbuf = abuf + TILE_BYTES;
#pragma unroll
        for (int ks = 0; ks < 4; ks++) {
            const uint32_t kb = (uint32_t)ks * 32;
            uint32_t ar[4][4];
            uint32_t br[4][2];
#pragma unroll
            for (int mt = 0; mt < 4; mt++)
                ldmx4(ar[mt], abuf + a_row_off + mt * (16 * 144) + kb);
#pragma unroll
            for (int p = 0; p < 2; p++) {
                uint32_t r[4];
                ldmx4(r, bbuf + b_row_off + p * (16 * 144) + kb);
                br[p * 2][0] = r[0]; br[p * 2][1] = r[1];
                br[p * 2 + 1][0] = r[2]; br[p * 2 + 1][1] = r[3];
            }
#pragma unroll
            for (int mt = 0; mt < 4; mt++)
#pragma unroll
                for (int nt = 0; nt < 4; nt++)
                    mma16816(acc[mt][nt], ar[mt], br[nt]);
        }
        if (++buf == 3) buf = 0;
    }
#undef PREFETCH

    const int lrow = lid >> 2;
    const int lcol = (lid & 3) * 2;
#pragma unroll
    for (int mt = 0; mt < 4; mt++) {
        const int gm = m0 + mbase + mt * 16 + lrow;
#pragma unroll
        for (int nt = 0; nt < 4; nt++) {
            const int gn = n0 + nbase + nt * 8 + lcol;
            if (MODE == 0) {
                const float b0 = bias[gn], b1 = bias[gn + 1];
                float2 v0 = {acc[mt][nt][0] + b0, acc[mt][nt][1] + b1};
                float2 v1 = {acc[mt][nt][2] + b0, acc[mt][nt][3] + b1};
                *(float2*)&C[(size_t)gm * D_MODEL + gn] = v0;
                *(float2*)&C[(size_t)(gm + 8) * D_MODEL + gn] = v1;
            } else {
                // QKV scatter: Q -> g_q, K/V -> present tail; float2 (dd, dd+1 same head)
                const float b0 = bias[gn], b1 = bias[gn + 1];
                const int sec = gn >> 10, fr = gn & 1023;
                const int hh = fr >> 6, dd = fr & 63;
#pragma unroll
                for (int e2 = 0; e2 < 2; e2++) {
                    const int row = gm + e2 * 8;
                    const int bb = row >> 11, s = row & 2047;
                    float2 w = {acc[mt][nt][e2 * 2 + 0] + b0,
                                acc[mt][nt][e2 * 2 + 1] + b1};
                    if (sec == 0)
                        *(float2*)&g_q[(((size_t)bb * NH + hh) * S_LEN + s) * HD + dd] = w;
                    else
                        *(float2*)&KV[((((size_t)bb * 2 + (sec - 1)) * NH + hh) * S_LEN + s) * HD + dd] = w;
                }
            }
        }
    }
}

// ---------------- flash attention: 128 threads, 8x4 microtile ----------------
// K/V/P tiles 64x64 f32 with XOR chunk swizzle; Q linear. 64 KB smem -> 3 CTAs/SM.
// 12 LDS.128 per 32 FFMA4 in both score and PV phases -> FMA-bound.
#define ATTN_SMEM_BYTES 65536

__global__ __launch_bounds__(128, 3) void attn_k(const float* __restrict__ KV)
{
    extern __shared__ float sm[];
    float* Qs = sm;                 // [64][64] linear
    float* Ks = sm + 4096;          // swizzled
    float* Vs = sm + 8192;          // swizzled
    float* Ps = sm + 12288;         // swizzled

    const int bid = blockIdx.x;
    const int qt = bid & 31;
    const int h  = (bid >> 5) & 15;
    const int b  = bid >> 9;
    const int qs = qt * 64;

    const int tid = threadIdx.x;
    const int tx = tid & 15;        // key-col / head-dim group (x4)
    const int ty = tid >> 4;        // 0..7: query-row group (x8)
    const int i0 = ty * 8;
    const int j0 = tx * 4;
    const int sK = tx & 7;
    const float scale = 0.125f;

    const float* Qg = g_q + (((size_t)b * NH + h) * S_LEN) * HD;
    const float* Kg = KV + ((((size_t)b * 2 + 0) * NH + h) * S_LEN) * HD;
    const float* Vg = KV + ((((size_t)b * 2 + 1) * NH + h) * S_LEN) * HD;

    // load Q tile (pre-scaled), linear
    for (int idx = tid; idx < 1024; idx += 128) {
        const int i = idx >> 4, dc = idx & 15;
        float4 v = *(const float4*)&Qg[(size_t)(qs + i) * HD + dc * 4];
        v.x *= scale; v.y *= scale; v.z *= scale; v.w *= scale;
        *(float4*)&Qs[i * 64 + dc * 4] = v;
    }

    float m_run[8], rsum[8], o[8][4];
#pragma unroll
    for (int r = 0; r < 8; r++) {
        m_run[r] = -1e29f;
        rsum[r] = 0.f;
#pragma unroll
        for (int c = 0; c < 4; c++) o[r][c] = 0.f;
    }

    for (int kt = 0; kt < 5; kt++) {
        const int ks = qs - 256 + kt * 64;
        if (ks + 64 <= 0) continue;

        __syncthreads();
        for (int idx = tid; idx < 1024; idx += 128) {
            const int j = idx >> 4, cc = idx & 15;
            const int gj = ks + j;
            const int pc = cc ^ ((j >> 2) & 7);
            if (gj >= 0) {
                *(float4*)&Ks[j * 64 + pc * 4] = *(const float4*)&Kg[(size_t)gj * HD + cc * 4];
                *(float4*)&Vs[j * 64 + pc * 4] = *(const float4*)&Vg[(size_t)gj * HD + cc * 4];
            } else {
                float4 z = make_float4(0.f, 0.f, 0.f, 0.f);
                *(float4*)&Ks[j * 64 + pc * 4] = z;
                *(float4*)&Vs[j * 64 + pc * 4] = z;
            }
        }
        __syncthreads();

        // ---- scores: s[r][c] = sum_d Q[i0+r][d] * K[j0+c][d] ----
        float s[8][4];
#pragma unroll
        for (int r = 0; r < 8; r++)
#pragma unroll
            for (int c = 0; c < 4; c++) s[r][c] = 0.f;
#pragma unroll 4
        for (int dc = 0; dc < 16; dc++) {
            float4 k4[4];
#pragma unroll
            for (int c = 0; c < 4; c++)
                k4[c] = *(const float4*)&Ks[(j0 + c) * 64 + (dc ^ sK) * 4];
#pragma unroll
            for (int r = 0; r < 8; r++) {
                const float4 q = *(const float4*)&Qs[(i0 + r) * 64 + dc * 4];
#pragma unroll
                for (int c = 0; c < 4; c++)
                    s[r][c] += q.x * k4[c].x + q.y * k4[c].y
                             + q.z * k4[c].z + q.w * k4[c].w;
            }
        }
        // mask
#pragma unroll
        for (int r = 0; r < 8; r++) {
            const int gi = qs + i0 + r;
#pragma unroll
            for (int c = 0; c < 4; c++) {
                const int gj = ks + j0 + c;
                const bool ok = (gj >= 0) && (gj <= gi) && (gj > gi - WINDOW);
                if (!ok) s[r][c] = -1e30f;
            }
        }

        // ---- per-row tile max (all-reduce over 16 tx lanes) ----
        float tmax[8];
#pragma unroll
        for (int r = 0; r < 8; r++) {
            float m = fmaxf(fmaxf(s[r][0], s[r][1]), fmaxf(s[r][2], s[r][3]));
#pragma unroll
            for (int w = 1; w < 16; w <<= 1)
                m = fmaxf(m, __shfl_xor_sync(0xffffffffu, m, w));
            tmax[r] = m;
        }

        // ---- online softmax update; P -> swizzled smem ----
#pragma unroll
        for (int r = 0; r < 8; r++) {
            const float m_new = fmaxf(m_run[r], tmax[r]);
            const float alpha = __expf(m_run[r] - m_new);
            const int sP = ((i0 + r) >> 2) & 7;
            float* prow = Ps + (i0 + r) * 64 + (tx ^ sP) * 4;
            float lsum = 0.f;
#pragma unroll
            for (int c = 0; c < 4; c++) {
                const float p = __expf(s[r][c] - m_new);
                prow[c] = p;
                lsum += p;
            }
#pragma unroll
            for (int w = 1; w < 16; w <<= 1)
                lsum += __shfl_xor_sync(0xffffffffu, lsum, w);
            rsum[r] = rsum[r] * alpha + lsum;
#pragma unroll
            for (int c = 0; c < 4; c++) o[r][c] *= alpha;
            m_run[r] = m_new;
        }
        __syncthreads();

        // ---- PV: o[r][c] += sum_j P[i0+r][j] * V[j][j0+c] ----
#pragma unroll 4
        for (int jc = 0; jc < 16; jc++) {
            float4 v4[4];
            const int sv = jc & 7;
#pragma unroll
            for (int jj = 0; jj < 4; jj++)
                v4[jj] = *(const float4*)&Vs[(jc * 4 + jj) * 64 + (tx ^ sv) * 4];
#pragma unroll
            for (int r = 0; r < 8; r++) {
                const int sP = ((i0 + r) >> 2) & 7;
                const float4 p = *(const float4*)&Ps[(i0 + r) * 64 + (jc ^ sP) * 4];
                o[r][0] += p.x * v4[0].x + p.y * v4[1].x + p.z * v4[2].x + p.w * v4[3].x;
                o[r][1] += p.x * v4[0].y + p.y * v4[1].y + p.z * v4[2].y + p.w * v4[3].y;
                o[r][2] += p.x * v4[0].z + p.y * v4[1].z + p.z * v4[2].z + p.w * v4[3].z;
                o[r][3] += p.x * v4[0].w + p.y * v4[1].w + p.z * v4[2].w + p.w * v4[3].w;
            }
        }
    }

    // fused epilogue: normalize, hi/hi/lo split bf16 into g_ahat (8B stores)
#pragma unroll
    for (int r = 0; r < 8; r++) {
        const float ri = 1.f / rsum[r];
        const size_t m = (size_t)b * S_LEN + qs + i0 + r;
        __nv_bfloat16* row = g_ahat + m * KEFF;
        const int k = h * HD + j0;
        float v0 = o[r][0] * ri, v1 = o[r][1] * ri;
        float v2 = o[r][2] * ri, v3 = o[r][3] * ri;
        float h0 = __bfloat162float(__float2bfloat16(v0));
        float h1 = __bfloat162float(__float2bfloat16(v1));
        float h2 = __bfloat162float(__float2bfloat16(v2));
        float h3 = __bfloat162float(__float2bfloat16(v3));
        uint2 H = {bf2pack(v0, v1), bf2pack(v2, v3)};
        uint2 L = {bf2pack(v0 - h0, v1 - h1), bf2pack(v2 - h2, v3 - h3)};
        *(uint2*)&row[k]        = H;
        *(uint2*)&row[1024 + k] = H;
        *(uint2*)&row[2048 + k] = L;
    }
}

// ---------------------------------------------------------------------------
extern "C" void kernel_launch(void* const* d_in, const int* in_sizes, int n_in,
                              void* d_out, int out_size)
{
    const float* x      = (const float*)d_in[0];
    const float* w_attn = (const float*)d_in[1];
    const float* b_attn = (const float*)d_in[2];
    const float* w_proj = (const float*)d_in[3];
    const float* b_proj = (const float*)d_in[4];
    float* out = (float*)d_out;
    float* kv  = out + OUT_ELEMS;

    cudaFuncSetAttribute(attn_k, cudaFuncAttributeMaxDynamicSharedMemorySize, ATTN_SMEM_BYTES);
    cudaFuncSetAttribute(gemm_mma<0>, cudaFuncAttributeMaxDynamicSharedMemorySize, GEMM_SMEM);
    cudaFuncSetAttribute(gemm_mma<1>, cudaFuncAttributeMaxDynamicSharedMemorySize, GEMM_SMEM);

    __nv_bfloat16 *xhat, *ahat, *wat, *wpt;
    cudaGetSymbolAddress((void**)&xhat, g_xhat);
    cudaGetSymbolAddress((void**)&ahat, g_ahat);
    cudaGetSymbolAddress((void**)&wat,  g_wat);
    cudaGetSymbolAddress((void**)&wpt,  g_wpt);

    // 1) split conversions of inputs (vectorized)
    convA_k<<<(TOKENS * 256 + 255) / 256, 256>>>(x, xhat, TOKENS * 256);
    {
        dim3 blk(8, 32);
        convBt_k<<<dim3(3 * D_MODEL / 32, D_MODEL / 32), blk>>>(w_attn, wat, 3 * D_MODEL);
        convBt_k<<<dim3(D_MODEL / 32, D_MODEL / 32),     blk>>>(w_proj, wpt, D_MODEL);
    }

    // 2) QKV projection: Q -> g_q, K/V -> present tail of d_out
    gemm_mma<1><<<dim3(3 * D_MODEL / 128, TOKENS / 128), 256, GEMM_SMEM>>>(
        xhat, wat, b_attn, nullptr, kv);

    // 3) flash sliding-window attention -> g_ahat (split bf16)
    attn_k<<<BATCH * NH * (S_LEN / 64), 128, ATTN_SMEM_BYTES>>>(kv);

    // 4) output projection -> d_out head
    gemm_mma<0><<<dim3(D_MODEL / 128, TOKENS / 128), 256, GEMM_SMEM>>>(
        ahat, wpt, b_proj, out, nullptr);
}